// round 13
// baseline (speedup 1.0000x reference)
#include <cuda_runtime.h>
#include <cuda_bf16.h>
#include <math.h>
#include <stdint.h>

#define BB 64
#define TT 512
#define DIN 862
#define HH 1024
#define GG 4096

#define NCTA 128

// ---------------- scratch (allocation-free rule: __device__ globals) ----------------
static __device__ float g_xg[(size_t)TT * BB * GG];          // [T*B][G] gate preactivations
static __device__ unsigned g_gen;
static __device__ unsigned g_cnt;
static __device__ __nv_bfloat16 g_Ahi[(size_t)TT * BB * 1024];
static __device__ __nv_bfloat16 g_Alo[(size_t)TT * BB * 1024];
static __device__ __nv_bfloat16 g_Whi[(size_t)GG * 1024];    // input-GEMM weights
static __device__ __nv_bfloat16 g_Wlo[(size_t)GG * 1024];
static __device__ __nv_bfloat16 g_Rhi[(size_t)GG * 1024];    // recurrent weights
static __device__ __nv_bfloat16 g_Rlo[(size_t)GG * 1024];
static __device__ __nv_bfloat16 g_ghi[2][BB * HH];           // h state bf16 hi, ping-pong [b][k]
static __device__ __nv_bfloat16 g_glo[2][BB * HH];           // h state bf16 lo

// ---------------- PTX helpers ----------------
__device__ __forceinline__ uint32_t smem_u32(const void* p) {
    uint32_t a;
    asm("{ .reg .u64 t; cvta.to.shared.u64 t, %1; cvt.u32.u64 %0, t; }" : "=r"(a) : "l"(p));
    return a;
}
__device__ __forceinline__ void cp_async16(uint32_t dst, const void* src) {
    asm volatile("cp.async.cg.shared.global [%0], [%1], 16;" :: "r"(dst), "l"(src));
}
__device__ __forceinline__ void cp_commit() { asm volatile("cp.async.commit_group;" ::: "memory"); }
template<int N> __device__ __forceinline__ void cp_wait() { asm volatile("cp.async.wait_group %0;" :: "n"(N) : "memory"); }

#define LDSM4(r, addr) \
    asm volatile("ldmatrix.sync.aligned.m8n8.x4.shared.b16 {%0,%1,%2,%3}, [%4];" \
        : "=r"((r)[0]), "=r"((r)[1]), "=r"((r)[2]), "=r"((r)[3]) : "r"(addr))

#define MMA16816(c, a, b) \
    asm volatile("mma.sync.aligned.m16n8k16.row.col.f32.bf16.bf16.f32 " \
        "{%0,%1,%2,%3}, {%4,%5,%6,%7}, {%8,%9}, {%0,%1,%2,%3};" \
        : "+f"((c)[0]), "+f"((c)[1]), "+f"((c)[2]), "+f"((c)[3]) \
        : "r"((a)[0]), "r"((a)[1]), "r"((a)[2]), "r"((a)[3]), "r"((b)[0]), "r"((b)[1]))

// ---------------- fp32 -> split bf16 conversions ----------------
__global__ void convW(const float* __restrict__ src, int K) {
    size_t i = (size_t)blockIdx.x * blockDim.x + threadIdx.x;
    if (i >= ((size_t)GG << 10)) return;
    int k = (int)(i & 1023);
    size_t row = i >> 10;
    float v = (k < K) ? src[row * K + k] : 0.f;
    __nv_bfloat16 h = __float2bfloat16(v);
    g_Whi[i] = h;
    g_Wlo[i] = __float2bfloat16(v - __bfloat162float(h));
}

#define NWELEM ((size_t)GG << 10)
#define NZ 131072
#define NAELEM ((size_t)TT * BB << 10)
__global__ void conv_all(const float* __restrict__ x, const float* __restrict__ Whh, int has_x) {
    size_t i = (size_t)blockIdx.x * blockDim.x + threadIdx.x;
    if (i < NWELEM) {
        int k = (int)(i & 1023);
        size_t row = i >> 10;
        float v = Whh[(row << 10) + k];
        __nv_bfloat16 h = __float2bfloat16(v);
        g_Rhi[i] = h;
        g_Rlo[i] = __float2bfloat16(v - __bfloat162float(h));
    } else if (i < NWELEM + NZ) {
        size_t z = i - NWELEM;
        if (z == 0) { g_gen = 0u; g_cnt = 0u; }
        if (z < 65536) ((uint32_t*)g_ghi)[z] = 0u;
        else           ((uint32_t*)g_glo)[z - 65536] = 0u;
    } else if (has_x) {
        size_t j = i - NWELEM - NZ;
        if (j < NAELEM) {
            int k = (int)(j & 1023);
            size_t row = j >> 10;
            int t = (int)(row >> 6), b = (int)(row & 63);
            float v = (k < DIN) ? x[((size_t)b * TT + t) * DIN + k] : 0.f;
            __nv_bfloat16 h = __float2bfloat16(v);
            g_Ahi[j] = h;
            g_Alo[j] = __float2bfloat16(v - __bfloat162float(h));
        }
    }
}

// ---------------- mma.sync bf16 split GEMM (round-9, passing) ----------------
#define TROW 144
#define TILE_B (128 * TROW)
#define STAGE_B (4 * TILE_B)
#define GEMM_SMEM (2 * STAGE_B + 512)

__device__ __forceinline__ void gemm_issue_loads(uint32_t sbase, int c, int m0, int n0, int tid) {
    const __nv_bfloat16* ptrs[4] = { g_Ahi, g_Alo, g_Whi, g_Wlo };
#pragma unroll
    for (int q = 0; q < 4; q++) {
        const __nv_bfloat16* p = ptrs[q];
        int rowbase = (q < 2) ? m0 : n0;
        uint32_t tb = sbase + q * TILE_B;
#pragma unroll
        for (int i = 0; i < 4; i++) {
            int idx = tid + i * 256;
            int r = idx >> 3, s = idx & 7;
            cp_async16(tb + r * TROW + s * 16,
                       p + (((size_t)(rowbase + r)) << 10) + (c << 6) + (s << 3));
        }
    }
}

__global__ void __launch_bounds__(256, 1)
gemm_bf16_split(const float* __restrict__ b1, const float* __restrict__ b2, int nch)
{
    extern __shared__ char smraw[];
    uint32_t sbase = smem_u32(smraw);
    float* sbias = (float*)(smraw + 2 * STAGE_B);

    const int tid = threadIdx.x;
    const int lane = tid & 31, wid = tid >> 5;
    const int n0 = blockIdx.x * 128;
    const int m0 = blockIdx.y * 128;
    const int wm = (wid >> 2) * 64;
    const int wn = (wid & 3) * 32;

    if (tid < 128) sbias[tid] = b1[n0 + tid] + b2[n0 + tid];

    float acc[4][4][4];
#pragma unroll
    for (int i = 0; i < 4; i++)
#pragma unroll
        for (int j = 0; j < 4; j++)
#pragma unroll
            for (int q = 0; q < 4; q++) acc[i][j][q] = 0.f;

    gemm_issue_loads(sbase, 0, m0, n0, tid);
    cp_commit();

    const uint32_t a_row = wm + (lane & 15);
    const uint32_t a_coh = (lane >> 4) << 4;
    const uint32_t b_rlo = (lane >> 4) * 8 + (lane & 7);
    const uint32_t b_coh = ((lane >> 3) & 1) << 4;

    for (int c = 0; c < nch; c++) {
        if (c < nch - 1) {
            gemm_issue_loads(sbase + ((c + 1) & 1) * STAGE_B, c + 1, m0, n0, tid);
            cp_commit();
            cp_wait<1>();
        } else {
            cp_wait<0>();
        }
        __syncthreads();

        const uint32_t buf = sbase + (c & 1) * STAGE_B;
        const uint32_t Ahi_b = buf;
        const uint32_t Alo_b = buf + TILE_B;
        const uint32_t Whi_b = buf + 2 * TILE_B;
        const uint32_t Wlo_b = buf + 3 * TILE_B;

#pragma unroll
        for (int ks = 0; ks < 4; ks++) {
            const uint32_t kso = ks * 32;
            uint32_t ah[4][4], bh[4][2];
#pragma unroll
            for (int mt = 0; mt < 4; mt++)
                LDSM4(ah[mt], Ahi_b + (a_row + mt * 16) * TROW + kso + a_coh);
#pragma unroll
            for (int g = 0; g < 2; g++) {
                uint32_t t4[4];
                LDSM4(t4, Whi_b + (wn + g * 16 + b_rlo) * TROW + kso + b_coh);
                bh[g * 2][0] = t4[0]; bh[g * 2][1] = t4[1];
                bh[g * 2 + 1][0] = t4[2]; bh[g * 2 + 1][1] = t4[3];
            }
#pragma unroll
            for (int mt = 0; mt < 4; mt++)
#pragma unroll
                for (int nt = 0; nt < 4; nt++)
                    MMA16816(acc[mt][nt], ah[mt], bh[nt]);

            uint32_t bl[4][2];
#pragma unroll
            for (int g = 0; g < 2; g++) {
                uint32_t t4[4];
                LDSM4(t4, Wlo_b + (wn + g * 16 + b_rlo) * TROW + kso + b_coh);
                bl[g * 2][0] = t4[0]; bl[g * 2][1] = t4[1];
                bl[g * 2 + 1][0] = t4[2]; bl[g * 2 + 1][1] = t4[3];
            }
#pragma unroll
            for (int mt = 0; mt < 4; mt++)
#pragma unroll
                for (int nt = 0; nt < 4; nt++)
                    MMA16816(acc[mt][nt], ah[mt], bl[nt]);

            uint32_t al[4][4];
#pragma unroll
            for (int mt = 0; mt < 4; mt++)
                LDSM4(al[mt], Alo_b + (a_row + mt * 16) * TROW + kso + a_coh);
#pragma unroll
            for (int mt = 0; mt < 4; mt++)
#pragma unroll
                for (int nt = 0; nt < 4; nt++)
                    MMA16816(acc[mt][nt], al[mt], bh[nt]);
        }
        __syncthreads();
    }

    const int r_lo = lane >> 2;
    const int cpos = (lane & 3) * 2;
#pragma unroll
    for (int mt = 0; mt < 4; mt++) {
        int row0 = m0 + wm + mt * 16 + r_lo;
#pragma unroll
        for (int nt = 0; nt < 4; nt++) {
            int cl = wn + nt * 8 + cpos;
            float bx = sbias[cl], by = sbias[cl + 1];
            float2 v0 = make_float2(acc[mt][nt][0] + bx, acc[mt][nt][1] + by);
            float2 v1 = make_float2(acc[mt][nt][2] + bx, acc[mt][nt][3] + by);
            *(float2*)&g_xg[(size_t)row0 * GG + n0 + cl] = v0;
            *(float2*)&g_xg[(size_t)(row0 + 8) * GG + n0 + cl] = v1;
        }
    }
}

// ---------------- persistent recurrence: 16 warps, 4-way k-split ----------------
// 128 CTAs x 512 threads. Warp (wb = wid&3, wk = wid>>2): batch rows
// [wb*16, wb*16+16), k range [wk*256, wk*256+256) in 8 chunks of 32 k.
// Partials combined via smem (aliased onto staging, freed after k-loop);
// wk==0 warps run the pointwise update.
#define WROW 2064
#define WS_B (32 * WROW)                // 66048 per array
#define RROW 80                         // 32 bf16 = 64B + 16B pad (conflict-free)
#define RBUF_B (16 * RROW)              // 1280
#define RSTG_B (2 * RBUF_B)             // 2560 (hi + lo)
#define NBUF 2
#define WARP_STG (NBUF * RSTG_B)        // 5120
#define REC_SMEM (2 * WS_B + 16 * WARP_STG)   // 214016

__device__ __forceinline__ void rec_stage_w(uint32_t dst, const __nv_bfloat16* ghi,
                                            const __nv_bfloat16* glo,
                                            int wb, int wk, int c, int lane) {
#pragma unroll
    for (int i = 0; i < 2; i++) {
        int idx = lane + i * 32;          // 0..63
        int r = idx >> 2, s = idx & 3;    // 16 rows x 4 x 16B
        uint32_t d = dst + r * RROW + s * 16;
        size_t so = (size_t)(wb * 16 + r) * 1024 + wk * 256 + c * 32 + s * 8;
        cp_async16(d, ghi + so);
        cp_async16(d + RBUF_B, glo + so);
    }
    cp_commit();
}

template<int LAYER>
__global__ void __launch_bounds__(512, 1)
lstm_rec_tc(float* __restrict__ out_ext)
{
    extern __shared__ char smraw[];
    const uint32_t sb = smem_u32(smraw);
    const uint32_t ws_hi = sb;
    const uint32_t ws_lo = sb + WS_B;
    float* cmb = (float*)(smraw + 2 * WS_B);   // aliases staging; used post-k-loop only

    const int tid = threadIdx.x;
    const int lane = tid & 31, wid = tid >> 5;
    const int wb = wid & 3;          // batch group
    const int wk = wid >> 2;         // k quarter (0..3)
    const int j0 = blockIdx.x * 8;
    const uint32_t wstg = sb + 2 * WS_B + wid * WARP_STG;

    // Load W tiles: 4 groups of 128 threads -> (hi/lo) x (rows 0-15 / 16-31)
    {
        const int tt = tid & 127;
        const int grp = tid >> 7;                // 0..3
        const __nv_bfloat16* src = (grp & 1) ? g_Rlo : g_Rhi;
        const uint32_t dstb = (grp & 1) ? ws_lo : ws_hi;
        const int half = grp >> 1;
#pragma unroll 4
        for (int n = 0; n < 16; n++) {
            int n2 = half * 16 + n;
            int grow = ((n2 >> 3) << 10) + j0 + (n2 & 7);
            cp_async16(dstb + n2 * WROW + tt * 16, src + ((size_t)grow << 10) + tt * 8);
        }
    }
    cp_commit(); cp_wait<0>();
    __syncthreads();

    const uint32_t a_off = (lane & 15) * RROW + ((lane >> 4) << 4);
    const uint32_t w_off = ((lane >> 4) * 8 + (lane & 7)) * WROW + (((lane >> 3) & 1) << 4);

    // cell mapping (wk==0 warps): acc[nt][0]=(r0,c0) [1]=(r0,c1) [2]=(r0+8,c0) [3]=(r0+8,c1)
    const int r0 = lane >> 2;
    const int c0 = (lane & 3) * 2;
    const int bA = wb * 16 + r0;
    const int bB = bA + 8;
    const int jj = j0 + c0;

    float cst[4] = {0.f, 0.f, 0.f, 0.f};
    unsigned gen = 0;

    for (int t = 0; t < TT; t++) {
        const __nv_bfloat16* ghi_in = g_ghi[t & 1];
        const __nv_bfloat16* glo_in = g_glo[t & 1];
        __nv_bfloat16* ghi_out = g_ghi[(t + 1) & 1];
        __nv_bfloat16* glo_out = g_glo[(t + 1) & 1];

        float2 xgv[2][4];
        if (wk == 0) {
#pragma unroll
            for (int rp = 0; rp < 2; rp++) {
                size_t base = ((size_t)t * BB + (rp ? bB : bA)) * GG + jj;
#pragma unroll
                for (int g = 0; g < 4; g++)
                    xgv[rp][g] = *(const float2*)&g_xg[base + (size_t)g * HH];
            }
        }

        float acc[4][4];
#pragma unroll
        for (int nt = 0; nt < 4; nt++)
#pragma unroll
            for (int q = 0; q < 4; q++) acc[nt][q] = 0.f;

        rec_stage_w(wstg, ghi_in, glo_in, wb, wk, 0, lane);

        for (int c = 0; c < 8; c++) {
            if (c < 7) {
                rec_stage_w(wstg + ((c + 1) & 1) * RSTG_B, ghi_in, glo_in, wb, wk, c + 1, lane);
                cp_wait<1>();
            } else {
                cp_wait<0>();
            }
            __syncwarp();

            const uint32_t abuf = wstg + (c & 1) * RSTG_B;
#pragma unroll
            for (int kl = 0; kl < 2; kl++) {
                const uint32_t Aad = abuf + a_off + kl * 32;
                const uint32_t kby = (uint32_t)(wk * 256 + c * 32 + kl * 16) * 2;

                uint32_t ah[4], al[4], bh[4][2], bl[4][2];
                LDSM4(ah, Aad);
                LDSM4(al, Aad + RBUF_B);
                {
                    uint32_t t4[4];
                    LDSM4(t4, ws_hi + w_off + kby);
                    bh[0][0] = t4[0]; bh[0][1] = t4[1]; bh[1][0] = t4[2]; bh[1][1] = t4[3];
                    LDSM4(t4, ws_hi + 16 * WROW + w_off + kby);
                    bh[2][0] = t4[0]; bh[2][1] = t4[1]; bh[3][0] = t4[2]; bh[3][1] = t4[3];
                    LDSM4(t4, ws_lo + w_off + kby);
                    bl[0][0] = t4[0]; bl[0][1] = t4[1]; bl[1][0] = t4[2]; bl[1][1] = t4[3];
                    LDSM4(t4, ws_lo + 16 * WROW + w_off + kby);
                    bl[2][0] = t4[0]; bl[2][1] = t4[1]; bl[3][0] = t4[2]; bl[3][1] = t4[3];
                }
#pragma unroll
                for (int nt = 0; nt < 4; nt++) {
                    MMA16816(acc[nt], ah, bh[nt]);
                    MMA16816(acc[nt], al, bh[nt]);
                    MMA16816(acc[nt], ah, bl[nt]);
                }
            }
        }

        // combine k-quarters: staging is idle now; cmb aliases it.
        __syncthreads();                       // all warps done reading staging
        if (wk != 0) {
            float* p = cmb + (((wk - 1) * 4 + wb) * 32 + lane) * 16;
#pragma unroll
            for (int nt = 0; nt < 4; nt++)
                *(float4*)(p + nt * 4) = make_float4(acc[nt][0], acc[nt][1], acc[nt][2], acc[nt][3]);
        }
        __syncthreads();

        if (wk == 0) {
#pragma unroll
            for (int src = 0; src < 3; src++) {
                float* p = cmb + ((src * 4 + wb) * 32 + lane) * 16;
#pragma unroll
                for (int nt = 0; nt < 4; nt++) {
                    float4 v = *(float4*)(p + nt * 4);
                    acc[nt][0] += v.x; acc[nt][1] += v.y; acc[nt][2] += v.z; acc[nt][3] += v.w;
                }
            }

#pragma unroll
            for (int rp = 0; rp < 2; rp++) {
                const int b = rp ? bB : bA;
                float hn[2];
#pragma unroll
                for (int cc = 0; cc < 2; cc++) {
                    const int q = rp * 2 + cc;
                    float pi = acc[0][q] + (cc ? xgv[rp][0].y : xgv[rp][0].x);
                    float pf = acc[1][q] + (cc ? xgv[rp][1].y : xgv[rp][1].x);
                    float pg = acc[2][q] + (cc ? xgv[rp][2].y : xgv[rp][2].x);
                    float po = acc[3][q] + (cc ? xgv[rp][3].y : xgv[rp][3].x);
                    float ig = 1.f / (1.f + expf(-pi));
                    float fg = 1.f / (1.f + expf(-pf));
                    float gc = tanhf(pg);
                    float og = 1.f / (1.f + expf(-po));
                    float cn = fg * cst[q] + ig * gc;
                    cst[q] = cn;
                    hn[cc] = og * tanhf(cn);
                }
                __nv_bfloat16 h0 = __float2bfloat16(hn[0]);
                __nv_bfloat16 h1 = __float2bfloat16(hn[1]);
                __nv_bfloat16 l0 = __float2bfloat16(hn[0] - __bfloat162float(h0));
                __nv_bfloat16 l1 = __float2bfloat16(hn[1] - __bfloat162float(h1));
                *(__nv_bfloat162*)&ghi_out[(size_t)b * HH + jj] = __nv_bfloat162(h0, h1);
                *(__nv_bfloat162*)&glo_out[(size_t)b * HH + jj] = __nv_bfloat162(l0, l1);
                if (LAYER == 0) {
                    size_t arow = (((size_t)t * BB + b) << 10) + jj;
                    *(__nv_bfloat162*)&g_Ahi[arow] = __nv_bfloat162(h0, h1);
                    *(__nv_bfloat162*)&g_Alo[arow] = __nv_bfloat162(l0, l1);
                } else {
                    *(float2*)&out_ext[((size_t)b * TT + t) * HH + jj] = make_float2(hn[0], hn[1]);
                }
            }
        }

        // ---- grid barrier (atomic version, proven) ----
        __threadfence();
        __syncthreads();
        gen++;
        if (tid == 0) {
            if (atomicAdd(&g_cnt, 1u) == NCTA - 1) {
                g_cnt = 0u;
                __threadfence();
                *(volatile unsigned*)&g_gen = gen;
            } else {
                while (*(volatile unsigned*)&g_gen < gen) { }
                __threadfence();
            }
        }
        __syncthreads();
    }
}

// ---------------- launch ----------------
extern "C" void kernel_launch(void* const* d_in, const int* in_sizes, int n_in,
                              void* d_out, int out_size)
{
    (void)in_sizes; (void)n_in; (void)out_size;
    const float* x     = (const float*)d_in[0];
    const float* W_ih0 = (const float*)d_in[1];
    const float* W_hh0 = (const float*)d_in[2];
    const float* b_ih0 = (const float*)d_in[3];
    const float* b_hh0 = (const float*)d_in[4];
    const float* W_ih1 = (const float*)d_in[5];
    const float* W_hh1 = (const float*)d_in[6];
    const float* b_ih1 = (const float*)d_in[7];
    const float* b_hh1 = (const float*)d_in[8];
    float* out = (float*)d_out;

    cudaFuncSetAttribute(gemm_bf16_split, cudaFuncAttributeMaxDynamicSharedMemorySize, GEMM_SMEM);
    cudaFuncSetAttribute(lstm_rec_tc<0>, cudaFuncAttributeMaxDynamicSharedMemorySize, REC_SMEM);
    cudaFuncSetAttribute(lstm_rec_tc<1>, cudaFuncAttributeMaxDynamicSharedMemorySize, REC_SMEM);

    dim3 gemm_grid(GG / 128, (TT * BB) / 128);
    const int nch0 = (DIN + 63) / 64;
    const int nch1 = 16;
    const size_t nW = (size_t)GG << 10;
    const int gridW = (int)((nW + 255) / 256);
    const int gridAll0 = (int)((NWELEM + NZ + NAELEM + 255) / 256);
    const int gridAll1 = (int)((NWELEM + NZ + 255) / 256);

    // ---- Layer 0 ----  (our launch index 3 = lstm_rec_tc<0> -> ncu capture target)
    convW<<<gridW, 256>>>(W_ih0, DIN);                                   // 0
    conv_all<<<gridAll0, 256>>>(x, W_hh0, 1);                            // 1
    gemm_bf16_split<<<gemm_grid, 256, GEMM_SMEM>>>(b_ih0, b_hh0, nch0);  // 2
    lstm_rec_tc<0><<<NCTA, 512, REC_SMEM>>>(out);                        // 3 <- profiled
    // ---- Layer 1 ----
    convW<<<gridW, 256>>>(W_ih1, HH);                                    // 4
    conv_all<<<gridAll1, 256>>>(nullptr, W_hh1, 0);                      // 5
    gemm_bf16_split<<<gemm_grid, 256, GEMM_SMEM>>>(b_ih1, b_hh1, nch1);  // 6
    lstm_rec_tc<1><<<NCTA, 512, REC_SMEM>>>(out);                        // 7
}

// round 14
// speedup vs baseline: 1.0492x; 1.0492x over previous
#include <cuda_runtime.h>
#include <cuda_bf16.h>
#include <math.h>
#include <stdint.h>

#define BB 64
#define TT 512
#define DIN 862
#define HH 1024
#define GG 4096

#define NCTA 128
#define NGRP 16
#define GRPSZ 8

// ---------------- scratch (allocation-free rule: __device__ globals) ----------------
static __device__ float g_xg[(size_t)TT * BB * GG];          // [T*B][G] gate preactivations
static __device__ unsigned g_gen;
static __device__ unsigned g_root;
static __device__ unsigned g_grp[NGRP];
static __device__ __nv_bfloat16 g_Ahi[(size_t)TT * BB * 1024];
static __device__ __nv_bfloat16 g_Alo[(size_t)TT * BB * 1024];
static __device__ __nv_bfloat16 g_Whi[(size_t)GG * 1024];    // input-GEMM weights
static __device__ __nv_bfloat16 g_Wlo[(size_t)GG * 1024];
static __device__ __nv_bfloat16 g_Rhi[(size_t)GG * 1024];    // recurrent weights
static __device__ __nv_bfloat16 g_Rlo[(size_t)GG * 1024];
static __device__ __nv_bfloat16 g_ghi[2][BB * HH];           // h state bf16 hi, ping-pong [b][k]
static __device__ __nv_bfloat16 g_glo[2][BB * HH];           // h state bf16 lo

// ---------------- PTX helpers ----------------
__device__ __forceinline__ uint32_t smem_u32(const void* p) {
    uint32_t a;
    asm("{ .reg .u64 t; cvta.to.shared.u64 t, %1; cvt.u32.u64 %0, t; }" : "=r"(a) : "l"(p));
    return a;
}
__device__ __forceinline__ void cp_async16(uint32_t dst, const void* src) {
    asm volatile("cp.async.cg.shared.global [%0], [%1], 16;" :: "r"(dst), "l"(src));
}
__device__ __forceinline__ void cp_commit() { asm volatile("cp.async.commit_group;" ::: "memory"); }
template<int N> __device__ __forceinline__ void cp_wait() { asm volatile("cp.async.wait_group %0;" :: "n"(N) : "memory"); }

#define LDSM4(r, addr) \
    asm volatile("ldmatrix.sync.aligned.m8n8.x4.shared.b16 {%0,%1,%2,%3}, [%4];" \
        : "=r"((r)[0]), "=r"((r)[1]), "=r"((r)[2]), "=r"((r)[3]) : "r"(addr))

#define MMA16816(c, a, b) \
    asm volatile("mma.sync.aligned.m16n8k16.row.col.f32.bf16.bf16.f32 " \
        "{%0,%1,%2,%3}, {%4,%5,%6,%7}, {%8,%9}, {%0,%1,%2,%3};" \
        : "+f"((c)[0]), "+f"((c)[1]), "+f"((c)[2]), "+f"((c)[3]) \
        : "r"((a)[0]), "r"((a)[1]), "r"((a)[2]), "r"((a)[3]), "r"((b)[0]), "r"((b)[1]))

// ---------------- fp32 -> split bf16 conversions ----------------
__global__ void convW(const float* __restrict__ src, int K) {
    size_t i = (size_t)blockIdx.x * blockDim.x + threadIdx.x;
    if (i >= ((size_t)GG << 10)) return;
    int k = (int)(i & 1023);
    size_t row = i >> 10;
    float v = (k < K) ? src[row * K + k] : 0.f;
    __nv_bfloat16 h = __float2bfloat16(v);
    g_Whi[i] = h;
    g_Wlo[i] = __float2bfloat16(v - __bfloat162float(h));
}

#define NWELEM ((size_t)GG << 10)
#define NZ 131072
#define NAELEM ((size_t)TT * BB << 10)
__global__ void conv_all(const float* __restrict__ x, const float* __restrict__ Whh, int has_x) {
    size_t i = (size_t)blockIdx.x * blockDim.x + threadIdx.x;
    if (i < NWELEM) {
        int k = (int)(i & 1023);
        size_t row = i >> 10;
        float v = Whh[(row << 10) + k];
        __nv_bfloat16 h = __float2bfloat16(v);
        g_Rhi[i] = h;
        g_Rlo[i] = __float2bfloat16(v - __bfloat162float(h));
    } else if (i < NWELEM + NZ) {
        size_t z = i - NWELEM;
        if (z == 0) {
            g_gen = 0u; g_root = 0u;
            for (int q = 0; q < NGRP; q++) g_grp[q] = 0u;
        }
        if (z < 65536) ((uint32_t*)g_ghi)[z] = 0u;
        else           ((uint32_t*)g_glo)[z - 65536] = 0u;
    } else if (has_x) {
        size_t j = i - NWELEM - NZ;
        if (j < NAELEM) {
            int k = (int)(j & 1023);
            size_t row = j >> 10;
            int t = (int)(row >> 6), b = (int)(row & 63);
            float v = (k < DIN) ? x[((size_t)b * TT + t) * DIN + k] : 0.f;
            __nv_bfloat16 h = __float2bfloat16(v);
            g_Ahi[j] = h;
            g_Alo[j] = __float2bfloat16(v - __bfloat162float(h));
        }
    }
}

// ---------------- mma.sync bf16 split GEMM (round-9, passing) ----------------
#define TROW 144
#define TILE_B (128 * TROW)
#define STAGE_B (4 * TILE_B)
#define GEMM_SMEM (2 * STAGE_B + 512)

__device__ __forceinline__ void gemm_issue_loads(uint32_t sbase, int c, int m0, int n0, int tid) {
    const __nv_bfloat16* ptrs[4] = { g_Ahi, g_Alo, g_Whi, g_Wlo };
#pragma unroll
    for (int q = 0; q < 4; q++) {
        const __nv_bfloat16* p = ptrs[q];
        int rowbase = (q < 2) ? m0 : n0;
        uint32_t tb = sbase + q * TILE_B;
#pragma unroll
        for (int i = 0; i < 4; i++) {
            int idx = tid + i * 256;
            int r = idx >> 3, s = idx & 7;
            cp_async16(tb + r * TROW + s * 16,
                       p + (((size_t)(rowbase + r)) << 10) + (c << 6) + (s << 3));
        }
    }
}

__global__ void __launch_bounds__(256, 1)
gemm_bf16_split(const float* __restrict__ b1, const float* __restrict__ b2, int nch)
{
    extern __shared__ char smraw[];
    uint32_t sbase = smem_u32(smraw);
    float* sbias = (float*)(smraw + 2 * STAGE_B);

    const int tid = threadIdx.x;
    const int lane = tid & 31, wid = tid >> 5;
    const int n0 = blockIdx.x * 128;
    const int m0 = blockIdx.y * 128;
    const int wm = (wid >> 2) * 64;
    const int wn = (wid & 3) * 32;

    if (tid < 128) sbias[tid] = b1[n0 + tid] + b2[n0 + tid];

    float acc[4][4][4];
#pragma unroll
    for (int i = 0; i < 4; i++)
#pragma unroll
        for (int j = 0; j < 4; j++)
#pragma unroll
            for (int q = 0; q < 4; q++) acc[i][j][q] = 0.f;

    gemm_issue_loads(sbase, 0, m0, n0, tid);
    cp_commit();

    const uint32_t a_row = wm + (lane & 15);
    const uint32_t a_coh = (lane >> 4) << 4;
    const uint32_t b_rlo = (lane >> 4) * 8 + (lane & 7);
    const uint32_t b_coh = ((lane >> 3) & 1) << 4;

    for (int c = 0; c < nch; c++) {
        if (c < nch - 1) {
            gemm_issue_loads(sbase + ((c + 1) & 1) * STAGE_B, c + 1, m0, n0, tid);
            cp_commit();
            cp_wait<1>();
        } else {
            cp_wait<0>();
        }
        __syncthreads();

        const uint32_t buf = sbase + (c & 1) * STAGE_B;
        const uint32_t Ahi_b = buf;
        const uint32_t Alo_b = buf + TILE_B;
        const uint32_t Whi_b = buf + 2 * TILE_B;
        const uint32_t Wlo_b = buf + 3 * TILE_B;

#pragma unroll
        for (int ks = 0; ks < 4; ks++) {
            const uint32_t kso = ks * 32;
            uint32_t ah[4][4], bh[4][2];
#pragma unroll
            for (int mt = 0; mt < 4; mt++)
                LDSM4(ah[mt], Ahi_b + (a_row + mt * 16) * TROW + kso + a_coh);
#pragma unroll
            for (int g = 0; g < 2; g++) {
                uint32_t t4[4];
                LDSM4(t4, Whi_b + (wn + g * 16 + b_rlo) * TROW + kso + b_coh);
                bh[g * 2][0] = t4[0]; bh[g * 2][1] = t4[1];
                bh[g * 2 + 1][0] = t4[2]; bh[g * 2 + 1][1] = t4[3];
            }
#pragma unroll
            for (int mt = 0; mt < 4; mt++)
#pragma unroll
                for (int nt = 0; nt < 4; nt++)
                    MMA16816(acc[mt][nt], ah[mt], bh[nt]);

            uint32_t bl[4][2];
#pragma unroll
            for (int g = 0; g < 2; g++) {
                uint32_t t4[4];
                LDSM4(t4, Wlo_b + (wn + g * 16 + b_rlo) * TROW + kso + b_coh);
                bl[g * 2][0] = t4[0]; bl[g * 2][1] = t4[1];
                bl[g * 2 + 1][0] = t4[2]; bl[g * 2 + 1][1] = t4[3];
            }
#pragma unroll
            for (int mt = 0; mt < 4; mt++)
#pragma unroll
                for (int nt = 0; nt < 4; nt++)
                    MMA16816(acc[mt][nt], ah[mt], bl[nt]);

            uint32_t al[4][4];
#pragma unroll
            for (int mt = 0; mt < 4; mt++)
                LDSM4(al[mt], Alo_b + (a_row + mt * 16) * TROW + kso + a_coh);
#pragma unroll
            for (int mt = 0; mt < 4; mt++)
#pragma unroll
                for (int nt = 0; nt < 4; nt++)
                    MMA16816(acc[mt][nt], al[mt], bh[nt]);
        }
        __syncthreads();
    }

    const int r_lo = lane >> 2;
    const int cpos = (lane & 3) * 2;
#pragma unroll
    for (int mt = 0; mt < 4; mt++) {
        int row0 = m0 + wm + mt * 16 + r_lo;
#pragma unroll
        for (int nt = 0; nt < 4; nt++) {
            int cl = wn + nt * 8 + cpos;
            float bx = sbias[cl], by = sbias[cl + 1];
            float2 v0 = make_float2(acc[mt][nt][0] + bx, acc[mt][nt][1] + by);
            float2 v1 = make_float2(acc[mt][nt][2] + bx, acc[mt][nt][3] + by);
            *(float2*)&g_xg[(size_t)row0 * GG + n0 + cl] = v0;
            *(float2*)&g_xg[(size_t)(row0 + 8) * GG + n0 + cl] = v1;
        }
    }
}

// ---------------- persistent recurrence: 8 warps, k-split pairs (round-12 best) ----------------
#define WROW 2064
#define WS_B (32 * WROW)
#define RROW 144
#define RBUF_B (16 * RROW)
#define RSTG_B (2 * RBUF_B)
#define NBUF 2
#define WARP_STG (NBUF * RSTG_B)
#define CMB_OFF (2 * WS_B + 8 * WARP_STG)
#define CMB_B (4 * 32 * 16 * 4)
#define REC_SMEM (CMB_OFF + CMB_B)

__device__ __forceinline__ void rec_stage_w(uint32_t dst, const __nv_bfloat16* ghi,
                                            const __nv_bfloat16* glo,
                                            int wb, int wk, int c, int lane) {
#pragma unroll
    for (int i = 0; i < 4; i++) {
        int idx = lane + i * 32;
        int r = idx >> 3, s = idx & 7;
        uint32_t d = dst + r * RROW + s * 16;
        size_t so = (size_t)(wb * 16 + r) * 1024 + wk * 512 + c * 64 + s * 8;
        cp_async16(d, ghi + so);
        cp_async16(d + RBUF_B, glo + so);
    }
    cp_commit();
}

template<int LAYER>
__global__ void __launch_bounds__(256, 1)
lstm_rec_tc(float* __restrict__ out_ext)
{
    extern __shared__ char smraw[];
    const uint32_t sb = smem_u32(smraw);
    const uint32_t ws_hi = sb;
    const uint32_t ws_lo = sb + WS_B;
    float* cmb = (float*)(smraw + CMB_OFF);

    const int tid = threadIdx.x;
    const int lane = tid & 31, wid = tid >> 5;
    const int wb = wid & 3;          // batch group
    const int wk = wid >> 2;         // k half
    const int j0 = blockIdx.x * 8;
    const uint32_t wstg = sb + 2 * WS_B + wid * WARP_STG;

    {
        const int tt = tid & 127;
        const __nv_bfloat16* src = (tid < 128) ? g_Rhi : g_Rlo;
        const uint32_t dstb = (tid < 128) ? ws_hi : ws_lo;
#pragma unroll 4
        for (int n = 0; n < 32; n++) {
            int grow = ((n >> 3) << 10) + j0 + (n & 7);
            cp_async16(dstb + n * WROW + tt * 16, src + ((size_t)grow << 10) + tt * 8);
        }
    }
    cp_commit(); cp_wait<0>();
    __syncthreads();

    const uint32_t a_off = (lane & 15) * RROW + ((lane >> 4) << 4);
    const uint32_t w_off = ((lane >> 4) * 8 + (lane & 7)) * WROW + (((lane >> 3) & 1) << 4);

    const int r0 = lane >> 2;
    const int c0 = (lane & 3) * 2;
    const int bA = wb * 16 + r0;
    const int bB = bA + 8;
    const int jj = j0 + c0;

    float cst[4] = {0.f, 0.f, 0.f, 0.f};
    unsigned gen = 0;

    for (int t = 0; t < TT; t++) {
        const __nv_bfloat16* ghi_in = g_ghi[t & 1];
        const __nv_bfloat16* glo_in = g_glo[t & 1];
        __nv_bfloat16* ghi_out = g_ghi[(t + 1) & 1];
        __nv_bfloat16* glo_out = g_glo[(t + 1) & 1];

        float2 xgv[2][4];
        if (wk == 0) {
#pragma unroll
            for (int rp = 0; rp < 2; rp++) {
                size_t base = ((size_t)t * BB + (rp ? bB : bA)) * GG + jj;
#pragma unroll
                for (int g = 0; g < 4; g++)
                    xgv[rp][g] = *(const float2*)&g_xg[base + (size_t)g * HH];
            }
        }

        float acc[4][4];
#pragma unroll
        for (int nt = 0; nt < 4; nt++)
#pragma unroll
            for (int q = 0; q < 4; q++) acc[nt][q] = 0.f;

        rec_stage_w(wstg, ghi_in, glo_in, wb, wk, 0, lane);

        for (int c = 0; c < 8; c++) {
            if (c < 7) {
                rec_stage_w(wstg + ((c + 1) & 1) * RSTG_B, ghi_in, glo_in, wb, wk, c + 1, lane);
                cp_wait<1>();
            } else {
                cp_wait<0>();
            }
            __syncwarp();

            const uint32_t abuf = wstg + (c & 1) * RSTG_B;
#pragma unroll
            for (int kl = 0; kl < 4; kl++) {
                const uint32_t Aad = abuf + a_off + kl * 32;
                const uint32_t kby = (uint32_t)(wk * 512 + c * 64 + kl * 16) * 2;

                uint32_t ah[4], al[4], bh[4][2], bl[4][2];
                LDSM4(ah, Aad);
                LDSM4(al, Aad + RBUF_B);
                {
                    uint32_t t4[4];
                    LDSM4(t4, ws_hi + w_off + kby);
                    bh[0][0] = t4[0]; bh[0][1] = t4[1]; bh[1][0] = t4[2]; bh[1][1] = t4[3];
                    LDSM4(t4, ws_hi + 16 * WROW + w_off + kby);
                    bh[2][0] = t4[0]; bh[2][1] = t4[1]; bh[3][0] = t4[2]; bh[3][1] = t4[3];
                    LDSM4(t4, ws_lo + w_off + kby);
                    bl[0][0] = t4[0]; bl[0][1] = t4[1]; bl[1][0] = t4[2]; bl[1][1] = t4[3];
                    LDSM4(t4, ws_lo + 16 * WROW + w_off + kby);
                    bl[2][0] = t4[0]; bl[2][1] = t4[1]; bl[3][0] = t4[2]; bl[3][1] = t4[3];
                }
#pragma unroll
                for (int nt = 0; nt < 4; nt++) {
                    MMA16816(acc[nt], ah, bh[nt]);
                    MMA16816(acc[nt], al, bh[nt]);
                    MMA16816(acc[nt], ah, bl[nt]);
                }
            }
        }

        // combine k-halves: warps 4-7 publish partials, warps 0-3 add
        if (wk == 1) {
            float* p = cmb + (wb * 32 + lane) * 16;
#pragma unroll
            for (int nt = 0; nt < 4; nt++)
                *(float4*)(p + nt * 4) = make_float4(acc[nt][0], acc[nt][1], acc[nt][2], acc[nt][3]);
        }
        __syncthreads();

        if (wk == 0) {
            float* p = cmb + (wb * 32 + lane) * 16;
#pragma unroll
            for (int nt = 0; nt < 4; nt++) {
                float4 v = *(float4*)(p + nt * 4);
                acc[nt][0] += v.x; acc[nt][1] += v.y; acc[nt][2] += v.z; acc[nt][3] += v.w;
            }

#pragma unroll
            for (int rp = 0; rp < 2; rp++) {
                const int b = rp ? bB : bA;
                float hn[2];
#pragma unroll
                for (int cc = 0; cc < 2; cc++) {
                    const int q = rp * 2 + cc;
                    float pi = acc[0][q] + (cc ? xgv[rp][0].y : xgv[rp][0].x);
                    float pf = acc[1][q] + (cc ? xgv[rp][1].y : xgv[rp][1].x);
                    float pg = acc[2][q] + (cc ? xgv[rp][2].y : xgv[rp][2].x);
                    float po = acc[3][q] + (cc ? xgv[rp][3].y : xgv[rp][3].x);
                    float ig = 1.f / (1.f + expf(-pi));
                    float fg = 1.f / (1.f + expf(-pf));
                    float gc = tanhf(pg);
                    float og = 1.f / (1.f + expf(-po));
                    float cn = fg * cst[q] + ig * gc;
                    cst[q] = cn;
                    hn[cc] = og * tanhf(cn);
                }
                __nv_bfloat16 h0 = __float2bfloat16(hn[0]);
                __nv_bfloat16 h1 = __float2bfloat16(hn[1]);
                __nv_bfloat16 l0 = __float2bfloat16(hn[0] - __bfloat162float(h0));
                __nv_bfloat16 l1 = __float2bfloat16(hn[1] - __bfloat162float(h1));
                *(__nv_bfloat162*)&ghi_out[(size_t)b * HH + jj] = __nv_bfloat162(h0, h1);
                *(__nv_bfloat162*)&glo_out[(size_t)b * HH + jj] = __nv_bfloat162(l0, l1);
                if (LAYER == 0) {
                    size_t arow = (((size_t)t * BB + b) << 10) + jj;
                    *(__nv_bfloat162*)&g_Ahi[arow] = __nv_bfloat162(h0, h1);
                    *(__nv_bfloat162*)&g_Alo[arow] = __nv_bfloat162(l0, l1);
                } else {
                    *(float2*)&out_ext[((size_t)b * TT + t) * HH + jj] = make_float2(hn[0], hn[1]);
                }
            }
        }

        // ---- two-level tree grid barrier (monotonic counters, no resets) ----
        __threadfence();
        __syncthreads();
        gen++;
        if (tid == 0) {
            const int grp = blockIdx.x >> 3;               // 16 groups of 8
            unsigned go = atomicAdd(&g_grp[grp], 1u);
            if ((go & (GRPSZ - 1)) == GRPSZ - 1) {         // last of group
                unsigned ro = atomicAdd(&g_root, 1u);
                if ((ro & (NGRP - 1)) == NGRP - 1) {       // last group
                    __threadfence();
                    asm volatile("st.release.gpu.global.u32 [%0], %1;"
                                 :: "l"(&g_gen), "r"(gen) : "memory");
                }
            }
            unsigned vv;
            do {
                asm volatile("ld.acquire.gpu.global.u32 %0, [%1];"
                             : "=r"(vv) : "l"(&g_gen) : "memory");
            } while (vv < gen);
        }
        __syncthreads();
    }
}

// ---------------- launch ----------------
extern "C" void kernel_launch(void* const* d_in, const int* in_sizes, int n_in,
                              void* d_out, int out_size)
{
    (void)in_sizes; (void)n_in; (void)out_size;
    const float* x     = (const float*)d_in[0];
    const float* W_ih0 = (const float*)d_in[1];
    const float* W_hh0 = (const float*)d_in[2];
    const float* b_ih0 = (const float*)d_in[3];
    const float* b_hh0 = (const float*)d_in[4];
    const float* W_ih1 = (const float*)d_in[5];
    const float* W_hh1 = (const float*)d_in[6];
    const float* b_ih1 = (const float*)d_in[7];
    const float* b_hh1 = (const float*)d_in[8];
    float* out = (float*)d_out;

    cudaFuncSetAttribute(gemm_bf16_split, cudaFuncAttributeMaxDynamicSharedMemorySize, GEMM_SMEM);
    cudaFuncSetAttribute(lstm_rec_tc<0>, cudaFuncAttributeMaxDynamicSharedMemorySize, REC_SMEM);
    cudaFuncSetAttribute(lstm_rec_tc<1>, cudaFuncAttributeMaxDynamicSharedMemorySize, REC_SMEM);

    dim3 gemm_grid(GG / 128, (TT * BB) / 128);
    const int nch0 = (DIN + 63) / 64;
    const int nch1 = 16;
    const size_t nW = (size_t)GG << 10;
    const int gridW = (int)((nW + 255) / 256);
    const int gridAll0 = (int)((NWELEM + NZ + NAELEM + 255) / 256);
    const int gridAll1 = (int)((NWELEM + NZ + 255) / 256);

    // ---- Layer 0 ----  (our launch index 3 = lstm_rec_tc<0> -> ncu capture target)
    convW<<<gridW, 256>>>(W_ih0, DIN);                                   // 0
    conv_all<<<gridAll0, 256>>>(x, W_hh0, 1);                            // 1
    gemm_bf16_split<<<gemm_grid, 256, GEMM_SMEM>>>(b_ih0, b_hh0, nch0);  // 2
    lstm_rec_tc<0><<<NCTA, 256, REC_SMEM>>>(out);                        // 3 <- profiled
    // ---- Layer 1 ----
    convW<<<gridW, 256>>>(W_ih1, HH);                                    // 4
    conv_all<<<gridAll1, 256>>>(nullptr, W_hh1, 0);                      // 5
    gemm_bf16_split<<<gemm_grid, 256, GEMM_SMEM>>>(b_ih1, b_hh1, nch1);  // 6
    lstm_rec_tc<1><<<NCTA, 256, REC_SMEM>>>(out);                        // 7
}

// round 15
// speedup vs baseline: 1.1073x; 1.0554x over previous
#include <cuda_runtime.h>
#include <cuda_bf16.h>
#include <math.h>
#include <stdint.h>

#define BB 64
#define TT 512
#define DIN 862
#define HH 1024
#define GG 4096

#define NCTA 128

// ---------------- scratch (allocation-free rule: __device__ globals) ----------------
static __device__ float g_xg[(size_t)TT * BB * GG];          // [T*B][G] gate preactivations
static __device__ unsigned g_gen;
static __device__ unsigned g_cnt;
static __device__ __nv_bfloat16 g_Ahi[(size_t)TT * BB * 1024];
static __device__ __nv_bfloat16 g_Alo[(size_t)TT * BB * 1024];
static __device__ __nv_bfloat16 g_Whi[(size_t)GG * 1024];    // input-GEMM weights
static __device__ __nv_bfloat16 g_Wlo[(size_t)GG * 1024];
static __device__ __nv_bfloat16 g_Rhi[(size_t)GG * 1024];    // recurrent weights
static __device__ __nv_bfloat16 g_Rlo[(size_t)GG * 1024];
static __device__ __nv_bfloat16 g_ghi[2][BB * HH];           // h state bf16 hi, ping-pong [b][k]
static __device__ __nv_bfloat16 g_glo[2][BB * HH];           // h state bf16 lo

// ---------------- PTX helpers ----------------
__device__ __forceinline__ uint32_t smem_u32(const void* p) {
    uint32_t a;
    asm("{ .reg .u64 t; cvta.to.shared.u64 t, %1; cvt.u32.u64 %0, t; }" : "=r"(a) : "l"(p));
    return a;
}
__device__ __forceinline__ void cp_async16(uint32_t dst, const void* src) {
    asm volatile("cp.async.cg.shared.global [%0], [%1], 16;" :: "r"(dst), "l"(src));
}
__device__ __forceinline__ void cp_commit() { asm volatile("cp.async.commit_group;" ::: "memory"); }
template<int N> __device__ __forceinline__ void cp_wait() { asm volatile("cp.async.wait_group %0;" :: "n"(N) : "memory"); }

#define LDSM4(r, addr) \
    asm volatile("ldmatrix.sync.aligned.m8n8.x4.shared.b16 {%0,%1,%2,%3}, [%4];" \
        : "=r"((r)[0]), "=r"((r)[1]), "=r"((r)[2]), "=r"((r)[3]) : "r"(addr))

#define MMA16816(c, a, b) \
    asm volatile("mma.sync.aligned.m16n8k16.row.col.f32.bf16.bf16.f32 " \
        "{%0,%1,%2,%3}, {%4,%5,%6,%7}, {%8,%9}, {%0,%1,%2,%3};" \
        : "+f"((c)[0]), "+f"((c)[1]), "+f"((c)[2]), "+f"((c)[3]) \
        : "r"((a)[0]), "r"((a)[1]), "r"((a)[2]), "r"((a)[3]), "r"((b)[0]), "r"((b)[1]))

// ---------------- fp32 -> split bf16 conversions ----------------
__global__ void convW(const float* __restrict__ src, int K) {
    size_t i = (size_t)blockIdx.x * blockDim.x + threadIdx.x;
    if (i >= ((size_t)GG << 10)) return;
    int k = (int)(i & 1023);
    size_t row = i >> 10;
    float v = (k < K) ? src[row * K + k] : 0.f;
    __nv_bfloat16 h = __float2bfloat16(v);
    g_Whi[i] = h;
    g_Wlo[i] = __float2bfloat16(v - __bfloat162float(h));
}

#define NWELEM ((size_t)GG << 10)
#define NZ 131072
#define NAELEM ((size_t)TT * BB << 10)
__global__ void conv_all(const float* __restrict__ x, const float* __restrict__ Whh, int has_x) {
    size_t i = (size_t)blockIdx.x * blockDim.x + threadIdx.x;
    if (i < NWELEM) {
        int k = (int)(i & 1023);
        size_t row = i >> 10;
        float v = Whh[(row << 10) + k];
        __nv_bfloat16 h = __float2bfloat16(v);
        g_Rhi[i] = h;
        g_Rlo[i] = __float2bfloat16(v - __bfloat162float(h));
    } else if (i < NWELEM + NZ) {
        size_t z = i - NWELEM;
        if (z == 0) { g_gen = 0u; g_cnt = 0u; }
        if (z < 65536) ((uint32_t*)g_ghi)[z] = 0u;
        else           ((uint32_t*)g_glo)[z - 65536] = 0u;
    } else if (has_x) {
        size_t j = i - NWELEM - NZ;
        if (j < NAELEM) {
            int k = (int)(j & 1023);
            size_t row = j >> 10;
            int t = (int)(row >> 6), b = (int)(row & 63);
            float v = (k < DIN) ? x[((size_t)b * TT + t) * DIN + k] : 0.f;
            __nv_bfloat16 h = __float2bfloat16(v);
            g_Ahi[j] = h;
            g_Alo[j] = __float2bfloat16(v - __bfloat162float(h));
        }
    }
}

// ---------------- mma.sync bf16 split GEMM, 3-stage pipeline, 1 sync/chunk ----------------
#define TROW 144
#define TILE_B (128 * TROW)           // 18432
#define STAGE_B (4 * TILE_B)          // 73728
#define GEMM_SMEM (3 * STAGE_B + 512) // 221696

__device__ __forceinline__ void gemm_issue_loads(uint32_t sbase, int c, int m0, int n0, int tid) {
    const __nv_bfloat16* ptrs[4] = { g_Ahi, g_Alo, g_Whi, g_Wlo };
#pragma unroll
    for (int q = 0; q < 4; q++) {
        const __nv_bfloat16* p = ptrs[q];
        int rowbase = (q < 2) ? m0 : n0;
        uint32_t tb = sbase + q * TILE_B;
#pragma unroll
        for (int i = 0; i < 4; i++) {
            int idx = tid + i * 256;
            int r = idx >> 3, s = idx & 7;
            cp_async16(tb + r * TROW + s * 16,
                       p + (((size_t)(rowbase + r)) << 10) + (c << 6) + (s << 3));
        }
    }
    cp_commit();
}

__global__ void __launch_bounds__(256, 1)
gemm_bf16_split(const float* __restrict__ b1, const float* __restrict__ b2, int nch)
{
    extern __shared__ char smraw[];
    uint32_t sbase = smem_u32(smraw);
    float* sbias = (float*)(smraw + 3 * STAGE_B);

    const int tid = threadIdx.x;
    const int lane = tid & 31, wid = tid >> 5;
    const int n0 = blockIdx.x * 128;
    const int m0 = blockIdx.y * 128;
    const int wm = (wid >> 2) * 64;
    const int wn = (wid & 3) * 32;

    if (tid < 128) sbias[tid] = b1[n0 + tid] + b2[n0 + tid];

    float acc[4][4][4];
#pragma unroll
    for (int i = 0; i < 4; i++)
#pragma unroll
        for (int j = 0; j < 4; j++)
#pragma unroll
            for (int q = 0; q < 4; q++) acc[i][j][q] = 0.f;

    // prologue: 2 stages in flight
    gemm_issue_loads(sbase, 0, m0, n0, tid);
    gemm_issue_loads(sbase + STAGE_B, 1, m0, n0, tid);

    const uint32_t a_row = wm + (lane & 15);
    const uint32_t a_coh = (lane >> 4) << 4;
    const uint32_t b_rlo = (lane >> 4) * 8 + (lane & 7);
    const uint32_t b_coh = ((lane >> 3) & 1) << 4;

    int bc = 0;   // compute buffer index (c % 3)
    for (int c = 0; c < nch; c++) {
        if (c < nch - 1) cp_wait<1>(); else cp_wait<0>();
        __syncthreads();
        if (c + 2 < nch) {
            int bi = bc + 2; if (bi >= 3) bi -= 3;
            gemm_issue_loads(sbase + bi * STAGE_B, c + 2, m0, n0, tid);
        }

        const uint32_t buf = sbase + bc * STAGE_B;
        const uint32_t Ahi_b = buf;
        const uint32_t Alo_b = buf + TILE_B;
        const uint32_t Whi_b = buf + 2 * TILE_B;
        const uint32_t Wlo_b = buf + 3 * TILE_B;

#pragma unroll
        for (int ks = 0; ks < 4; ks++) {
            const uint32_t kso = ks * 32;
            uint32_t ah[4][4], bh[4][2];
#pragma unroll
            for (int mt = 0; mt < 4; mt++)
                LDSM4(ah[mt], Ahi_b + (a_row + mt * 16) * TROW + kso + a_coh);
#pragma unroll
            for (int g = 0; g < 2; g++) {
                uint32_t t4[4];
                LDSM4(t4, Whi_b + (wn + g * 16 + b_rlo) * TROW + kso + b_coh);
                bh[g * 2][0] = t4[0]; bh[g * 2][1] = t4[1];
                bh[g * 2 + 1][0] = t4[2]; bh[g * 2 + 1][1] = t4[3];
            }
#pragma unroll
            for (int mt = 0; mt < 4; mt++)
#pragma unroll
                for (int nt = 0; nt < 4; nt++)
                    MMA16816(acc[mt][nt], ah[mt], bh[nt]);

            uint32_t bl[4][2];
#pragma unroll
            for (int g = 0; g < 2; g++) {
                uint32_t t4[4];
                LDSM4(t4, Wlo_b + (wn + g * 16 + b_rlo) * TROW + kso + b_coh);
                bl[g * 2][0] = t4[0]; bl[g * 2][1] = t4[1];
                bl[g * 2 + 1][0] = t4[2]; bl[g * 2 + 1][1] = t4[3];
            }
#pragma unroll
            for (int mt = 0; mt < 4; mt++)
#pragma unroll
                for (int nt = 0; nt < 4; nt++)
                    MMA16816(acc[mt][nt], ah[mt], bl[nt]);

            uint32_t al[4][4];
#pragma unroll
            for (int mt = 0; mt < 4; mt++)
                LDSM4(al[mt], Alo_b + (a_row + mt * 16) * TROW + kso + a_coh);
#pragma unroll
            for (int mt = 0; mt < 4; mt++)
#pragma unroll
                for (int nt = 0; nt < 4; nt++)
                    MMA16816(acc[mt][nt], al[mt], bh[nt]);
        }
        if (++bc == 3) bc = 0;
    }

    const int r_lo = lane >> 2;
    const int cpos = (lane & 3) * 2;
#pragma unroll
    for (int mt = 0; mt < 4; mt++) {
        int row0 = m0 + wm + mt * 16 + r_lo;
#pragma unroll
        for (int nt = 0; nt < 4; nt++) {
            int cl = wn + nt * 8 + cpos;
            float bx = sbias[cl], by = sbias[cl + 1];
            float2 v0 = make_float2(acc[mt][nt][0] + bx, acc[mt][nt][1] + by);
            float2 v1 = make_float2(acc[mt][nt][2] + bx, acc[mt][nt][3] + by);
            *(float2*)&g_xg[(size_t)row0 * GG + n0 + cl] = v0;
            *(float2*)&g_xg[(size_t)(row0 + 8) * GG + n0 + cl] = v1;
        }
    }
}

// ---------------- persistent recurrence: 8 warps, k-split pairs (round-12 best, unchanged) ----------------
#define WROW 2064
#define WS_B (32 * WROW)
#define RROW 144
#define RBUF_B (16 * RROW)
#define RSTG_B (2 * RBUF_B)
#define NBUF 2
#define WARP_STG (NBUF * RSTG_B)
#define CMB_OFF (2 * WS_B + 8 * WARP_STG)
#define CMB_B (4 * 32 * 16 * 4)
#define REC_SMEM (CMB_OFF + CMB_B)

__device__ __forceinline__ void rec_stage_w(uint32_t dst, const __nv_bfloat16* ghi,
                                            const __nv_bfloat16* glo,
                                            int wb, int wk, int c, int lane) {
#pragma unroll
    for (int i = 0; i < 4; i++) {
        int idx = lane + i * 32;
        int r = idx >> 3, s = idx & 7;
        uint32_t d = dst + r * RROW + s * 16;
        size_t so = (size_t)(wb * 16 + r) * 1024 + wk * 512 + c * 64 + s * 8;
        cp_async16(d, ghi + so);
        cp_async16(d + RBUF_B, glo + so);
    }
    cp_commit();
}

template<int LAYER>
__global__ void __launch_bounds__(256, 1)
lstm_rec_tc(float* __restrict__ out_ext)
{
    extern __shared__ char smraw[];
    const uint32_t sb = smem_u32(smraw);
    const uint32_t ws_hi = sb;
    const uint32_t ws_lo = sb + WS_B;
    float* cmb = (float*)(smraw + CMB_OFF);

    const int tid = threadIdx.x;
    const int lane = tid & 31, wid = tid >> 5;
    const int wb = wid & 3;          // batch group
    const int wk = wid >> 2;         // k half
    const int j0 = blockIdx.x * 8;
    const uint32_t wstg = sb + 2 * WS_B + wid * WARP_STG;

    {
        const int tt = tid & 127;
        const __nv_bfloat16* src = (tid < 128) ? g_Rhi : g_Rlo;
        const uint32_t dstb = (tid < 128) ? ws_hi : ws_lo;
#pragma unroll 4
        for (int n = 0; n < 32; n++) {
            int grow = ((n >> 3) << 10) + j0 + (n & 7);
            cp_async16(dstb + n * WROW + tt * 16, src + ((size_t)grow << 10) + tt * 8);
        }
    }
    cp_commit(); cp_wait<0>();
    __syncthreads();

    const uint32_t a_off = (lane & 15) * RROW + ((lane >> 4) << 4);
    const uint32_t w_off = ((lane >> 4) * 8 + (lane & 7)) * WROW + (((lane >> 3) & 1) << 4);

    const int r0 = lane >> 2;
    const int c0 = (lane & 3) * 2;
    const int bA = wb * 16 + r0;
    const int bB = bA + 8;
    const int jj = j0 + c0;

    float cst[4] = {0.f, 0.f, 0.f, 0.f};
    unsigned gen = 0;

    for (int t = 0; t < TT; t++) {
        const __nv_bfloat16* ghi_in = g_ghi[t & 1];
        const __nv_bfloat16* glo_in = g_glo[t & 1];
        __nv_bfloat16* ghi_out = g_ghi[(t + 1) & 1];
        __nv_bfloat16* glo_out = g_glo[(t + 1) & 1];

        float2 xgv[2][4];
        if (wk == 0) {
#pragma unroll
            for (int rp = 0; rp < 2; rp++) {
                size_t base = ((size_t)t * BB + (rp ? bB : bA)) * GG + jj;
#pragma unroll
                for (int g = 0; g < 4; g++)
                    xgv[rp][g] = *(const float2*)&g_xg[base + (size_t)g * HH];
            }
        }

        float acc[4][4];
#pragma unroll
        for (int nt = 0; nt < 4; nt++)
#pragma unroll
            for (int q = 0; q < 4; q++) acc[nt][q] = 0.f;

        rec_stage_w(wstg, ghi_in, glo_in, wb, wk, 0, lane);

        for (int c = 0; c < 8; c++) {
            if (c < 7) {
                rec_stage_w(wstg + ((c + 1) & 1) * RSTG_B, ghi_in, glo_in, wb, wk, c + 1, lane);
                cp_wait<1>();
            } else {
                cp_wait<0>();
            }
            __syncwarp();

            const uint32_t abuf = wstg + (c & 1) * RSTG_B;
#pragma unroll
            for (int kl = 0; kl < 4; kl++) {
                const uint32_t Aad = abuf + a_off + kl * 32;
                const uint32_t kby = (uint32_t)(wk * 512 + c * 64 + kl * 16) * 2;

                uint32_t ah[4], al[4], bh[4][2], bl[4][2];
                LDSM4(ah, Aad);
                LDSM4(al, Aad + RBUF_B);
                {
                    uint32_t t4[4];
                    LDSM4(t4, ws_hi + w_off + kby);
                    bh[0][0] = t4[0]; bh[0][1] = t4[1]; bh[1][0] = t4[2]; bh[1][1] = t4[3];
                    LDSM4(t4, ws_hi + 16 * WROW + w_off + kby);
                    bh[2][0] = t4[0]; bh[2][1] = t4[1]; bh[3][0] = t4[2]; bh[3][1] = t4[3];
                    LDSM4(t4, ws_lo + w_off + kby);
                    bl[0][0] = t4[0]; bl[0][1] = t4[1]; bl[1][0] = t4[2]; bl[1][1] = t4[3];
                    LDSM4(t4, ws_lo + 16 * WROW + w_off + kby);
                    bl[2][0] = t4[0]; bl[2][1] = t4[1]; bl[3][0] = t4[2]; bl[3][1] = t4[3];
                }
#pragma unroll
                for (int nt = 0; nt < 4; nt++) {
                    MMA16816(acc[nt], ah, bh[nt]);
                    MMA16816(acc[nt], al, bh[nt]);
                    MMA16816(acc[nt], ah, bl[nt]);
                }
            }
        }

        // combine k-halves: warps 4-7 publish partials, warps 0-3 add
        if (wk == 1) {
            float* p = cmb + (wb * 32 + lane) * 16;
#pragma unroll
            for (int nt = 0; nt < 4; nt++)
                *(float4*)(p + nt * 4) = make_float4(acc[nt][0], acc[nt][1], acc[nt][2], acc[nt][3]);
        }
        __syncthreads();

        if (wk == 0) {
            float* p = cmb + (wb * 32 + lane) * 16;
#pragma unroll
            for (int nt = 0; nt < 4; nt++) {
                float4 v = *(float4*)(p + nt * 4);
                acc[nt][0] += v.x; acc[nt][1] += v.y; acc[nt][2] += v.z; acc[nt][3] += v.w;
            }

#pragma unroll
            for (int rp = 0; rp < 2; rp++) {
                const int b = rp ? bB : bA;
                float hn[2];
#pragma unroll
                for (int cc = 0; cc < 2; cc++) {
                    const int q = rp * 2 + cc;
                    float pi = acc[0][q] + (cc ? xgv[rp][0].y : xgv[rp][0].x);
                    float pf = acc[1][q] + (cc ? xgv[rp][1].y : xgv[rp][1].x);
                    float pg = acc[2][q] + (cc ? xgv[rp][2].y : xgv[rp][2].x);
                    float po = acc[3][q] + (cc ? xgv[rp][3].y : xgv[rp][3].x);
                    float ig = 1.f / (1.f + expf(-pi));
                    float fg = 1.f / (1.f + expf(-pf));
                    float gc = tanhf(pg);
                    float og = 1.f / (1.f + expf(-po));
                    float cn = fg * cst[q] + ig * gc;
                    cst[q] = cn;
                    hn[cc] = og * tanhf(cn);
                }
                __nv_bfloat16 h0 = __float2bfloat16(hn[0]);
                __nv_bfloat16 h1 = __float2bfloat16(hn[1]);
                __nv_bfloat16 l0 = __float2bfloat16(hn[0] - __bfloat162float(h0));
                __nv_bfloat16 l1 = __float2bfloat16(hn[1] - __bfloat162float(h1));
                *(__nv_bfloat162*)&ghi_out[(size_t)b * HH + jj] = __nv_bfloat162(h0, h1);
                *(__nv_bfloat162*)&glo_out[(size_t)b * HH + jj] = __nv_bfloat162(l0, l1);
                if (LAYER == 0) {
                    size_t arow = (((size_t)t * BB + b) << 10) + jj;
                    *(__nv_bfloat162*)&g_Ahi[arow] = __nv_bfloat162(h0, h1);
                    *(__nv_bfloat162*)&g_Alo[arow] = __nv_bfloat162(l0, l1);
                } else {
                    *(float2*)&out_ext[((size_t)b * TT + t) * HH + jj] = make_float2(hn[0], hn[1]);
                }
            }
        }

        // ---- grid barrier (central atomic, proven best) ----
        __threadfence();
        __syncthreads();
        gen++;
        if (tid == 0) {
            if (atomicAdd(&g_cnt, 1u) == NCTA - 1) {
                g_cnt = 0u;
                __threadfence();
                *(volatile unsigned*)&g_gen = gen;
            } else {
                while (*(volatile unsigned*)&g_gen < gen) { }
                __threadfence();
            }
        }
        __syncthreads();
    }
}

// ---------------- launch ----------------
extern "C" void kernel_launch(void* const* d_in, const int* in_sizes, int n_in,
                              void* d_out, int out_size)
{
    (void)in_sizes; (void)n_in; (void)out_size;
    const float* x     = (const float*)d_in[0];
    const float* W_ih0 = (const float*)d_in[1];
    const float* W_hh0 = (const float*)d_in[2];
    const float* b_ih0 = (const float*)d_in[3];
    const float* b_hh0 = (const float*)d_in[4];
    const float* W_ih1 = (const float*)d_in[5];
    const float* W_hh1 = (const float*)d_in[6];
    const float* b_ih1 = (const float*)d_in[7];
    const float* b_hh1 = (const float*)d_in[8];
    float* out = (float*)d_out;

    cudaFuncSetAttribute(gemm_bf16_split, cudaFuncAttributeMaxDynamicSharedMemorySize, GEMM_SMEM);
    cudaFuncSetAttribute(lstm_rec_tc<0>, cudaFuncAttributeMaxDynamicSharedMemorySize, REC_SMEM);
    cudaFuncSetAttribute(lstm_rec_tc<1>, cudaFuncAttributeMaxDynamicSharedMemorySize, REC_SMEM);

    dim3 gemm_grid(GG / 128, (TT * BB) / 128);
    const int nch0 = (DIN + 63) / 64;   // 14 chunks cover k<896; rest is zero padding
    const int nch1 = 16;
    const size_t nW = (size_t)GG << 10;
    const int gridW = (int)((nW + 255) / 256);
    const int gridAll0 = (int)((NWELEM + NZ + NAELEM + 255) / 256);
    const int gridAll1 = (int)((NWELEM + NZ + 255) / 256);

    // ---- Layer 0 ----  (our launch index 3 = lstm_rec_tc<0> -> ncu capture target)
    convW<<<gridW, 256>>>(W_ih0, DIN);                                   // 0
    conv_all<<<gridAll0, 256>>>(x, W_hh0, 1);                            // 1
    gemm_bf16_split<<<gemm_grid, 256, GEMM_SMEM>>>(b_ih0, b_hh0, nch0);  // 2
    lstm_rec_tc<0><<<NCTA, 256, REC_SMEM>>>(out);                        // 3 <- profiled
    // ---- Layer 1 ----
    convW<<<gridW, 256>>>(W_ih1, HH);                                    // 4
    conv_all<<<gridAll1, 256>>>(nullptr, W_hh1, 0);                      // 5
    gemm_bf16_split<<<gemm_grid, 256, GEMM_SMEM>>>(b_ih1, b_hh1, nch1);  // 6
    lstm_rec_tc<1><<<NCTA, 256, REC_SMEM>>>(out);                        // 7
}

// round 16
// speedup vs baseline: 1.1102x; 1.0026x over previous
#include <cuda_runtime.h>
#include <cuda_bf16.h>
#include <math.h>
#include <stdint.h>

#define BB 64
#define TT 512
#define DIN 862
#define HH 1024
#define GG 4096

#define NCTA 128

// ---------------- scratch (allocation-free rule: __device__ globals) ----------------
static __device__ float g_xg[(size_t)TT * BB * GG];          // [T*B][G] gate preactivations
static __device__ unsigned g_gen;
static __device__ unsigned g_cnt;
static __device__ __nv_bfloat16 g_Ahi[(size_t)TT * BB * 1024];
static __device__ __nv_bfloat16 g_Alo[(size_t)TT * BB * 1024];
static __device__ __nv_bfloat16 g_Whi[(size_t)GG * 1024];    // input-GEMM weights
static __device__ __nv_bfloat16 g_Wlo[(size_t)GG * 1024];
static __device__ __nv_bfloat16 g_Rhi[(size_t)GG * 1024];    // recurrent weights
static __device__ __nv_bfloat16 g_Rlo[(size_t)GG * 1024];
static __device__ __nv_bfloat16 g_ghi[2][BB * HH];           // h state bf16 hi, ping-pong [b][k]
static __device__ __nv_bfloat16 g_glo[2][BB * HH];           // h state bf16 lo

// ---------------- PTX helpers ----------------
__device__ __forceinline__ uint32_t smem_u32(const void* p) {
    uint32_t a;
    asm("{ .reg .u64 t; cvta.to.shared.u64 t, %1; cvt.u32.u64 %0, t; }" : "=r"(a) : "l"(p));
    return a;
}
__device__ __forceinline__ void cp_async16(uint32_t dst, const void* src) {
    asm volatile("cp.async.cg.shared.global [%0], [%1], 16;" :: "r"(dst), "l"(src));
}
__device__ __forceinline__ void cp_commit() { asm volatile("cp.async.commit_group;" ::: "memory"); }
template<int N> __device__ __forceinline__ void cp_wait() { asm volatile("cp.async.wait_group %0;" :: "n"(N) : "memory"); }

#define LDSM4(r, addr) \
    asm volatile("ldmatrix.sync.aligned.m8n8.x4.shared.b16 {%0,%1,%2,%3}, [%4];" \
        : "=r"((r)[0]), "=r"((r)[1]), "=r"((r)[2]), "=r"((r)[3]) : "r"(addr))

#define MMA16816(c, a, b) \
    asm volatile("mma.sync.aligned.m16n8k16.row.col.f32.bf16.bf16.f32 " \
        "{%0,%1,%2,%3}, {%4,%5,%6,%7}, {%8,%9}, {%0,%1,%2,%3};" \
        : "+f"((c)[0]), "+f"((c)[1]), "+f"((c)[2]), "+f"((c)[3]) \
        : "r"((a)[0]), "r"((a)[1]), "r"((a)[2]), "r"((a)[3]), "r"((b)[0]), "r"((b)[1]))

#define BARPAIR(id) asm volatile("bar.sync %0, 64;" :: "r"(id) : "memory")

// ---------------- fp32 -> split bf16 conversions ----------------
__global__ void convW(const float* __restrict__ src, int K) {
    size_t i = (size_t)blockIdx.x * blockDim.x + threadIdx.x;
    if (i >= ((size_t)GG << 10)) return;
    int k = (int)(i & 1023);
    size_t row = i >> 10;
    float v = (k < K) ? src[row * K + k] : 0.f;
    __nv_bfloat16 h = __float2bfloat16(v);
    g_Whi[i] = h;
    g_Wlo[i] = __float2bfloat16(v - __bfloat162float(h));
}

#define NWELEM ((size_t)GG << 10)
#define NZ 131072
#define NAELEM ((size_t)TT * BB << 10)
__global__ void conv_all(const float* __restrict__ x, const float* __restrict__ Whh, int has_x) {
    size_t i = (size_t)blockIdx.x * blockDim.x + threadIdx.x;
    if (i < NWELEM) {
        int k = (int)(i & 1023);
        size_t row = i >> 10;
        float v = Whh[(row << 10) + k];
        __nv_bfloat16 h = __float2bfloat16(v);
        g_Rhi[i] = h;
        g_Rlo[i] = __float2bfloat16(v - __bfloat162float(h));
    } else if (i < NWELEM + NZ) {
        size_t z = i - NWELEM;
        if (z == 0) { g_gen = 0u; g_cnt = 0u; }
        if (z < 65536) ((uint32_t*)g_ghi)[z] = 0u;
        else           ((uint32_t*)g_glo)[z - 65536] = 0u;
    } else if (has_x) {
        size_t j = i - NWELEM - NZ;
        if (j < NAELEM) {
            int k = (int)(j & 1023);
            size_t row = j >> 10;
            int t = (int)(row >> 6), b = (int)(row & 63);
            float v = (k < DIN) ? x[((size_t)b * TT + t) * DIN + k] : 0.f;
            __nv_bfloat16 h = __float2bfloat16(v);
            g_Ahi[j] = h;
            g_Alo[j] = __float2bfloat16(v - __bfloat162float(h));
        }
    }
}

// ---------------- mma.sync bf16 split GEMM, 3-stage pipeline (r15, passing) ----------------
#define TROW 144
#define TILE_B (128 * TROW)
#define STAGE_B (4 * TILE_B)
#define GEMM_SMEM (3 * STAGE_B + 512)

__device__ __forceinline__ void gemm_issue_loads(uint32_t sbase, int c, int m0, int n0, int tid) {
    const __nv_bfloat16* ptrs[4] = { g_Ahi, g_Alo, g_Whi, g_Wlo };
#pragma unroll
    for (int q = 0; q < 4; q++) {
        const __nv_bfloat16* p = ptrs[q];
        int rowbase = (q < 2) ? m0 : n0;
        uint32_t tb = sbase + q * TILE_B;
#pragma unroll
        for (int i = 0; i < 4; i++) {
            int idx = tid + i * 256;
            int r = idx >> 3, s = idx & 7;
            cp_async16(tb + r * TROW + s * 16,
                       p + (((size_t)(rowbase + r)) << 10) + (c << 6) + (s << 3));
        }
    }
    cp_commit();
}

__global__ void __launch_bounds__(256, 1)
gemm_bf16_split(const float* __restrict__ b1, const float* __restrict__ b2, int nch)
{
    extern __shared__ char smraw[];
    uint32_t sbase = smem_u32(smraw);
    float* sbias = (float*)(smraw + 3 * STAGE_B);

    const int tid = threadIdx.x;
    const int lane = tid & 31, wid = tid >> 5;
    const int n0 = blockIdx.x * 128;
    const int m0 = blockIdx.y * 128;
    const int wm = (wid >> 2) * 64;
    const int wn = (wid & 3) * 32;

    if (tid < 128) sbias[tid] = b1[n0 + tid] + b2[n0 + tid];

    float acc[4][4][4];
#pragma unroll
    for (int i = 0; i < 4; i++)
#pragma unroll
        for (int j = 0; j < 4; j++)
#pragma unroll
            for (int q = 0; q < 4; q++) acc[i][j][q] = 0.f;

    gemm_issue_loads(sbase, 0, m0, n0, tid);
    gemm_issue_loads(sbase + STAGE_B, 1, m0, n0, tid);

    const uint32_t a_row = wm + (lane & 15);
    const uint32_t a_coh = (lane >> 4) << 4;
    const uint32_t b_rlo = (lane >> 4) * 8 + (lane & 7);
    const uint32_t b_coh = ((lane >> 3) & 1) << 4;

    int bc = 0;
    for (int c = 0; c < nch; c++) {
        if (c < nch - 1) cp_wait<1>(); else cp_wait<0>();
        __syncthreads();
        if (c + 2 < nch) {
            int bi = bc + 2; if (bi >= 3) bi -= 3;
            gemm_issue_loads(sbase + bi * STAGE_B, c + 2, m0, n0, tid);
        }

        const uint32_t buf = sbase + bc * STAGE_B;
        const uint32_t Ahi_b = buf;
        const uint32_t Alo_b = buf + TILE_B;
        const uint32_t Whi_b = buf + 2 * TILE_B;
        const uint32_t Wlo_b = buf + 3 * TILE_B;

#pragma unroll
        for (int ks = 0; ks < 4; ks++) {
            const uint32_t kso = ks * 32;
            uint32_t ah[4][4], bh[4][2];
#pragma unroll
            for (int mt = 0; mt < 4; mt++)
                LDSM4(ah[mt], Ahi_b + (a_row + mt * 16) * TROW + kso + a_coh);
#pragma unroll
            for (int g = 0; g < 2; g++) {
                uint32_t t4[4];
                LDSM4(t4, Whi_b + (wn + g * 16 + b_rlo) * TROW + kso + b_coh);
                bh[g * 2][0] = t4[0]; bh[g * 2][1] = t4[1];
                bh[g * 2 + 1][0] = t4[2]; bh[g * 2 + 1][1] = t4[3];
            }
#pragma unroll
            for (int mt = 0; mt < 4; mt++)
#pragma unroll
                for (int nt = 0; nt < 4; nt++)
                    MMA16816(acc[mt][nt], ah[mt], bh[nt]);

            uint32_t bl[4][2];
#pragma unroll
            for (int g = 0; g < 2; g++) {
                uint32_t t4[4];
                LDSM4(t4, Wlo_b + (wn + g * 16 + b_rlo) * TROW + kso + b_coh);
                bl[g * 2][0] = t4[0]; bl[g * 2][1] = t4[1];
                bl[g * 2 + 1][0] = t4[2]; bl[g * 2 + 1][1] = t4[3];
            }
#pragma unroll
            for (int mt = 0; mt < 4; mt++)
#pragma unroll
                for (int nt = 0; nt < 4; nt++)
                    MMA16816(acc[mt][nt], ah[mt], bl[nt]);

            uint32_t al[4][4];
#pragma unroll
            for (int mt = 0; mt < 4; mt++)
                LDSM4(al[mt], Alo_b + (a_row + mt * 16) * TROW + kso + a_coh);
#pragma unroll
            for (int mt = 0; mt < 4; mt++)
#pragma unroll
                for (int nt = 0; nt < 4; nt++)
                    MMA16816(acc[mt][nt], al[mt], bh[nt]);
        }
        if (++bc == 3) bc = 0;
    }

    const int r_lo = lane >> 2;
    const int cpos = (lane & 3) * 2;
#pragma unroll
    for (int mt = 0; mt < 4; mt++) {
        int row0 = m0 + wm + mt * 16 + r_lo;
#pragma unroll
        for (int nt = 0; nt < 4; nt++) {
            int cl = wn + nt * 8 + cpos;
            float bx = sbias[cl], by = sbias[cl + 1];
            float2 v0 = make_float2(acc[mt][nt][0] + bx, acc[mt][nt][1] + by);
            float2 v1 = make_float2(acc[mt][nt][2] + bx, acc[mt][nt][3] + by);
            *(float2*)&g_xg[(size_t)row0 * GG + n0 + cl] = v0;
            *(float2*)&g_xg[(size_t)(row0 + 8) * GG + n0 + cl] = v1;
        }
    }
}

// ---------------- persistent recurrence: 8 warps, k-split pairs ----------------
// r12 structure + (a) split correction accumulator accC (shorter MMA dep chains)
//                + (b) pairwise named-barrier combine (decouples warp pairs).
#define WROW 2064
#define WS_B (32 * WROW)
#define RROW 144
#define RBUF_B (16 * RROW)
#define RSTG_B (2 * RBUF_B)
#define NBUF 2
#define WARP_STG (NBUF * RSTG_B)
#define CMB_OFF (2 * WS_B + 8 * WARP_STG)
#define CMB_B (4 * 32 * 16 * 4)
#define REC_SMEM (CMB_OFF + CMB_B)

__device__ __forceinline__ void rec_stage_w(uint32_t dst, const __nv_bfloat16* ghi,
                                            const __nv_bfloat16* glo,
                                            int wb, int wk, int c, int lane) {
#pragma unroll
    for (int i = 0; i < 4; i++) {
        int idx = lane + i * 32;
        int r = idx >> 3, s = idx & 7;
        uint32_t d = dst + r * RROW + s * 16;
        size_t so = (size_t)(wb * 16 + r) * 1024 + wk * 512 + c * 64 + s * 8;
        cp_async16(d, ghi + so);
        cp_async16(d + RBUF_B, glo + so);
    }
    cp_commit();
}

template<int LAYER>
__global__ void __launch_bounds__(256, 1)
lstm_rec_tc(float* __restrict__ out_ext)
{
    extern __shared__ char smraw[];
    const uint32_t sb = smem_u32(smraw);
    const uint32_t ws_hi = sb;
    const uint32_t ws_lo = sb + WS_B;
    float* cmb = (float*)(smraw + CMB_OFF);

    const int tid = threadIdx.x;
    const int lane = tid & 31, wid = tid >> 5;
    const int wb = wid & 3;          // batch group
    const int wk = wid >> 2;         // k half
    const int j0 = blockIdx.x * 8;
    const uint32_t wstg = sb + 2 * WS_B + wid * WARP_STG;

    {
        const int tt = tid & 127;
        const __nv_bfloat16* src = (tid < 128) ? g_Rhi : g_Rlo;
        const uint32_t dstb = (tid < 128) ? ws_hi : ws_lo;
#pragma unroll 4
        for (int n = 0; n < 32; n++) {
            int grow = ((n >> 3) << 10) + j0 + (n & 7);
            cp_async16(dstb + n * WROW + tt * 16, src + ((size_t)grow << 10) + tt * 8);
        }
    }
    cp_commit(); cp_wait<0>();
    __syncthreads();

    const uint32_t a_off = (lane & 15) * RROW + ((lane >> 4) << 4);
    const uint32_t w_off = ((lane >> 4) * 8 + (lane & 7)) * WROW + (((lane >> 3) & 1) << 4);

    const int r0 = lane >> 2;
    const int c0 = (lane & 3) * 2;
    const int bA = wb * 16 + r0;
    const int bB = bA + 8;
    const int jj = j0 + c0;

    float cst[4] = {0.f, 0.f, 0.f, 0.f};
    unsigned gen = 0;

    for (int t = 0; t < TT; t++) {
        const __nv_bfloat16* ghi_in = g_ghi[t & 1];
        const __nv_bfloat16* glo_in = g_glo[t & 1];
        __nv_bfloat16* ghi_out = g_ghi[(t + 1) & 1];
        __nv_bfloat16* glo_out = g_glo[(t + 1) & 1];

        float2 xgv[2][4];
        if (wk == 0) {
#pragma unroll
            for (int rp = 0; rp < 2; rp++) {
                size_t base = ((size_t)t * BB + (rp ? bB : bA)) * GG + jj;
#pragma unroll
                for (int g = 0; g < 4; g++)
                    xgv[rp][g] = *(const float2*)&g_xg[base + (size_t)g * HH];
            }
        }

        float acc[4][4], accC[4][4];
#pragma unroll
        for (int nt = 0; nt < 4; nt++)
#pragma unroll
            for (int q = 0; q < 4; q++) { acc[nt][q] = 0.f; accC[nt][q] = 0.f; }

        rec_stage_w(wstg, ghi_in, glo_in, wb, wk, 0, lane);

        for (int c = 0; c < 8; c++) {
            if (c < 7) {
                rec_stage_w(wstg + ((c + 1) & 1) * RSTG_B, ghi_in, glo_in, wb, wk, c + 1, lane);
                cp_wait<1>();
            } else {
                cp_wait<0>();
            }
            __syncwarp();

            const uint32_t abuf = wstg + (c & 1) * RSTG_B;
#pragma unroll
            for (int kl = 0; kl < 4; kl++) {
                const uint32_t Aad = abuf + a_off + kl * 32;
                const uint32_t kby = (uint32_t)(wk * 512 + c * 64 + kl * 16) * 2;

                uint32_t ah[4], al[4], bh[4][2], bl[4][2];
                LDSM4(ah, Aad);
                LDSM4(al, Aad + RBUF_B);
                {
                    uint32_t t4[4];
                    LDSM4(t4, ws_hi + w_off + kby);
                    bh[0][0] = t4[0]; bh[0][1] = t4[1]; bh[1][0] = t4[2]; bh[1][1] = t4[3];
                    LDSM4(t4, ws_hi + 16 * WROW + w_off + kby);
                    bh[2][0] = t4[0]; bh[2][1] = t4[1]; bh[3][0] = t4[2]; bh[3][1] = t4[3];
                    LDSM4(t4, ws_lo + w_off + kby);
                    bl[0][0] = t4[0]; bl[0][1] = t4[1]; bl[1][0] = t4[2]; bl[1][1] = t4[3];
                    LDSM4(t4, ws_lo + 16 * WROW + w_off + kby);
                    bl[2][0] = t4[0]; bl[2][1] = t4[1]; bl[3][0] = t4[2]; bl[3][1] = t4[3];
                }
                // main pass and corrections on SEPARATE accumulators: 3 independent
                // dep chains per nt instead of one 3-deep chain per kl.
#pragma unroll
                for (int nt = 0; nt < 4; nt++) {
                    MMA16816(acc[nt],  ah, bh[nt]);
                    MMA16816(accC[nt], al, bh[nt]);
                    MMA16816(accC[nt], ah, bl[nt]);
                }
            }
        }

        // pairwise combine: only warps (wb, wb+4) need to meet (named barrier 1+wb)
        if (wk == 1) {
            float* p = cmb + (wb * 32 + lane) * 16;
#pragma unroll
            for (int nt = 0; nt < 4; nt++)
                *(float4*)(p + nt * 4) = make_float4(acc[nt][0] + accC[nt][0],
                                                     acc[nt][1] + accC[nt][1],
                                                     acc[nt][2] + accC[nt][2],
                                                     acc[nt][3] + accC[nt][3]);
        }
        BARPAIR(1 + wb);

        if (wk == 0) {
            float* p = cmb + (wb * 32 + lane) * 16;
#pragma unroll
            for (int nt = 0; nt < 4; nt++) {
                float4 v = *(float4*)(p + nt * 4);
                acc[nt][0] += accC[nt][0] + v.x;
                acc[nt][1] += accC[nt][1] + v.y;
                acc[nt][2] += accC[nt][2] + v.z;
                acc[nt][3] += accC[nt][3] + v.w;
            }

#pragma unroll
            for (int rp = 0; rp < 2; rp++) {
                const int b = rp ? bB : bA;
                float hn[2];
#pragma unroll
                for (int cc = 0; cc < 2; cc++) {
                    const int q = rp * 2 + cc;
                    float pi = acc[0][q] + (cc ? xgv[rp][0].y : xgv[rp][0].x);
                    float pf = acc[1][q] + (cc ? xgv[rp][1].y : xgv[rp][1].x);
                    float pg = acc[2][q] + (cc ? xgv[rp][2].y : xgv[rp][2].x);
                    float po = acc[3][q] + (cc ? xgv[rp][3].y : xgv[rp][3].x);
                    float ig = 1.f / (1.f + expf(-pi));
                    float fg = 1.f / (1.f + expf(-pf));
                    float gc = tanhf(pg);
                    float og = 1.f / (1.f + expf(-po));
                    float cn = fg * cst[q] + ig * gc;
                    cst[q] = cn;
                    hn[cc] = og * tanhf(cn);
                }
                __nv_bfloat16 h0 = __float2bfloat16(hn[0]);
                __nv_bfloat16 h1 = __float2bfloat16(hn[1]);
                __nv_bfloat16 l0 = __float2bfloat16(hn[0] - __bfloat162float(h0));
                __nv_bfloat16 l1 = __float2bfloat16(hn[1] - __bfloat162float(h1));
                *(__nv_bfloat162*)&ghi_out[(size_t)b * HH + jj] = __nv_bfloat162(h0, h1);
                *(__nv_bfloat162*)&glo_out[(size_t)b * HH + jj] = __nv_bfloat162(l0, l1);
                if (LAYER == 0) {
                    size_t arow = (((size_t)t * BB + b) << 10) + jj;
                    *(__nv_bfloat162*)&g_Ahi[arow] = __nv_bfloat162(h0, h1);
                    *(__nv_bfloat162*)&g_Alo[arow] = __nv_bfloat162(l0, l1);
                } else {
                    *(float2*)&out_ext[((size_t)b * TT + t) * HH + jj] = make_float2(hn[0], hn[1]);
                }
            }
        }

        // ---- grid barrier (central atomic, proven best) ----
        __threadfence();
        __syncthreads();
        gen++;
        if (tid == 0) {
            if (atomicAdd(&g_cnt, 1u) == NCTA - 1) {
                g_cnt = 0u;
                __threadfence();
                *(volatile unsigned*)&g_gen = gen;
            } else {
                while (*(volatile unsigned*)&g_gen < gen) { }
                __threadfence();
            }
        }
        __syncthreads();
    }
}

// ---------------- launch ----------------
extern "C" void kernel_launch(void* const* d_in, const int* in_sizes, int n_in,
                              void* d_out, int out_size)
{
    (void)in_sizes; (void)n_in; (void)out_size;
    const float* x     = (const float*)d_in[0];
    const float* W_ih0 = (const float*)d_in[1];
    const float* W_hh0 = (const float*)d_in[2];
    const float* b_ih0 = (const float*)d_in[3];
    const float* b_hh0 = (const float*)d_in[4];
    const float* W_ih1 = (const float*)d_in[5];
    const float* W_hh1 = (const float*)d_in[6];
    const float* b_ih1 = (const float*)d_in[7];
    const float* b_hh1 = (const float*)d_in[8];
    float* out = (float*)d_out;

    cudaFuncSetAttribute(gemm_bf16_split, cudaFuncAttributeMaxDynamicSharedMemorySize, GEMM_SMEM);
    cudaFuncSetAttribute(lstm_rec_tc<0>, cudaFuncAttributeMaxDynamicSharedMemorySize, REC_SMEM);
    cudaFuncSetAttribute(lstm_rec_tc<1>, cudaFuncAttributeMaxDynamicSharedMemorySize, REC_SMEM);

    dim3 gemm_grid(GG / 128, (TT * BB) / 128);
    const int nch0 = (DIN + 63) / 64;   // 14 chunks cover k<896; rest is zero padding
    const int nch1 = 16;
    const size_t nW = (size_t)GG << 10;
    const int gridW = (int)((nW + 255) / 256);
    const int gridAll0 = (int)((NWELEM + NZ + NAELEM + 255) / 256);
    const int gridAll1 = (int)((NWELEM + NZ + 255) / 256);

    // ---- Layer 0 ----  (our launch index 3 = lstm_rec_tc<0> -> ncu capture target)
    convW<<<gridW, 256>>>(W_ih0, DIN);                                   // 0
    conv_all<<<gridAll0, 256>>>(x, W_hh0, 1);                            // 1
    gemm_bf16_split<<<gemm_grid, 256, GEMM_SMEM>>>(b_ih0, b_hh0, nch0);  // 2
    lstm_rec_tc<0><<<NCTA, 256, REC_SMEM>>>(out);                        // 3 <- profiled
    // ---- Layer 1 ----
    convW<<<gridW, 256>>>(W_ih1, HH);                                    // 4
    conv_all<<<gridAll1, 256>>>(nullptr, W_hh1, 0);                      // 5
    gemm_bf16_split<<<gemm_grid, 256, GEMM_SMEM>>>(b_ih1, b_hh1, nch1);  // 6
    lstm_rec_tc<1><<<NCTA, 256, REC_SMEM>>>(out);                        // 7
}

// round 17
// speedup vs baseline: 1.1362x; 1.0234x over previous
#include <cuda_runtime.h>
#include <cuda_bf16.h>
#include <math.h>
#include <stdint.h>

#define BB 64
#define TT 512
#define DIN 862
#define HH 1024
#define GG 4096

#define NCTA 128

// ---------------- scratch (allocation-free rule: __device__ globals) ----------------
static __device__ float g_xg[(size_t)TT * BB * GG];          // [T*B][G] gate preactivations
static __device__ unsigned g_gen;
static __device__ unsigned g_cnt;
static __device__ __nv_bfloat16 g_Ahi[(size_t)TT * BB * 1024];
static __device__ __nv_bfloat16 g_Alo[(size_t)TT * BB * 1024];
static __device__ __nv_bfloat16 g_Whi[(size_t)GG * 1024];    // input-GEMM weights
static __device__ __nv_bfloat16 g_Wlo[(size_t)GG * 1024];
static __device__ __nv_bfloat16 g_Rhi[(size_t)GG * 1024];    // recurrent weights
static __device__ __nv_bfloat16 g_Rlo[(size_t)GG * 1024];
static __device__ __nv_bfloat16 g_ghi[2][BB * HH];           // h state bf16 hi, ping-pong [b][k]
static __device__ __nv_bfloat16 g_glo[2][BB * HH];           // h state bf16 lo

// ---------------- PTX helpers ----------------
__device__ __forceinline__ uint32_t smem_u32(const void* p) {
    uint32_t a;
    asm("{ .reg .u64 t; cvta.to.shared.u64 t, %1; cvt.u32.u64 %0, t; }" : "=r"(a) : "l"(p));
    return a;
}
__device__ __forceinline__ void cp_async16(uint32_t dst, const void* src) {
    asm volatile("cp.async.cg.shared.global [%0], [%1], 16;" :: "r"(dst), "l"(src));
}
__device__ __forceinline__ void cp_commit() { asm volatile("cp.async.commit_group;" ::: "memory"); }
template<int N> __device__ __forceinline__ void cp_wait() { asm volatile("cp.async.wait_group %0;" :: "n"(N) : "memory"); }

#define LDSM4(r, addr) \
    asm volatile("ldmatrix.sync.aligned.m8n8.x4.shared.b16 {%0,%1,%2,%3}, [%4];" \
        : "=r"((r)[0]), "=r"((r)[1]), "=r"((r)[2]), "=r"((r)[3]) : "r"(addr))

#define MMA16816(c, a, b) \
    asm volatile("mma.sync.aligned.m16n8k16.row.col.f32.bf16.bf16.f32 " \
        "{%0,%1,%2,%3}, {%4,%5,%6,%7}, {%8,%9}, {%0,%1,%2,%3};" \
        : "+f"((c)[0]), "+f"((c)[1]), "+f"((c)[2]), "+f"((c)[3]) \
        : "r"((a)[0]), "r"((a)[1]), "r"((a)[2]), "r"((a)[3]), "r"((b)[0]), "r"((b)[1]))

#define BARPAIR(id) asm volatile("bar.sync %0, 64;" :: "r"(id) : "memory")

// ---------------- fp32 -> split bf16 conversions ----------------
__global__ void convW(const float* __restrict__ src, int K) {
    size_t i = (size_t)blockIdx.x * blockDim.x + threadIdx.x;
    if (i >= ((size_t)GG << 10)) return;
    int k = (int)(i & 1023);
    size_t row = i >> 10;
    float v = (k < K) ? src[row * K + k] : 0.f;
    __nv_bfloat16 h = __float2bfloat16(v);
    g_Whi[i] = h;
    g_Wlo[i] = __float2bfloat16(v - __bfloat162float(h));
}

#define NWELEM ((size_t)GG << 10)
#define NZ 131072
#define NAELEM ((size_t)TT * BB << 10)
__global__ void conv_all(const float* __restrict__ x, const float* __restrict__ Whh, int has_x) {
    size_t i = (size_t)blockIdx.x * blockDim.x + threadIdx.x;
    if (i < NWELEM) {
        int k = (int)(i & 1023);
        size_t row = i >> 10;
        float v = Whh[(row << 10) + k];
        __nv_bfloat16 h = __float2bfloat16(v);
        g_Rhi[i] = h;
        g_Rlo[i] = __float2bfloat16(v - __bfloat162float(h));
    } else if (i < NWELEM + NZ) {
        size_t z = i - NWELEM;
        if (z == 0) { g_gen = 0u; g_cnt = 0u; }
        if (z < 65536) ((uint32_t*)g_ghi)[z] = 0u;
        else           ((uint32_t*)g_glo)[z - 65536] = 0u;
    } else if (has_x) {
        size_t j = i - NWELEM - NZ;
        if (j < NAELEM) {
            int k = (int)(j & 1023);
            size_t row = j >> 10;
            int t = (int)(row >> 6), b = (int)(row & 63);
            float v = (k < DIN) ? x[((size_t)b * TT + t) * DIN + k] : 0.f;
            __nv_bfloat16 h = __float2bfloat16(v);
            g_Ahi[j] = h;
            g_Alo[j] = __float2bfloat16(v - __bfloat162float(h));
        }
    }
}

// ---------------- mma.sync bf16 split GEMM: 256x128 tiles, 512 threads ----------------
// L2-traffic cut: per-chunk stage = A 256 rows + W 128 rows (hi+lo), amortizing A
// over twice the m. 16 warps, warp tile 64x32 (4m x 4n). 2 stages.
#define TROW 144
#define A_TILE (256 * TROW)           // 36864
#define W_TILE (128 * TROW)           // 18432
#define G_STAGE (2 * A_TILE + 2 * W_TILE)   // 110592
#define GEMM_SMEM (2 * G_STAGE + 512)       // 221696

__device__ __forceinline__ void gemm_issue_loads(uint32_t sbase, int c, int m0, int n0, int tid) {
    // A hi/lo: 256 rows x 8 sectors = 2048 ops each
#pragma unroll
    for (int q = 0; q < 2; q++) {
        const __nv_bfloat16* p = q ? g_Alo : g_Ahi;
        uint32_t tb = sbase + q * A_TILE;
#pragma unroll
        for (int i = 0; i < 4; i++) {
            int idx = tid + i * 512;
            int r = idx >> 3, s = idx & 7;
            cp_async16(tb + r * TROW + s * 16,
                       p + (((size_t)(m0 + r)) << 10) + (c << 6) + (s << 3));
        }
    }
    // W hi/lo: 128 rows x 8 sectors = 1024 ops each
#pragma unroll
    for (int q = 0; q < 2; q++) {
        const __nv_bfloat16* p = q ? g_Wlo : g_Whi;
        uint32_t tb = sbase + 2 * A_TILE + q * W_TILE;
#pragma unroll
        for (int i = 0; i < 2; i++) {
            int idx = tid + i * 512;
            int r = idx >> 3, s = idx & 7;
            cp_async16(tb + r * TROW + s * 16,
                       p + (((size_t)(n0 + r)) << 10) + (c << 6) + (s << 3));
        }
    }
    cp_commit();
}

__global__ void __launch_bounds__(512, 1)
gemm_bf16_split(const float* __restrict__ b1, const float* __restrict__ b2, int nch)
{
    extern __shared__ char smraw[];
    uint32_t sbase = smem_u32(smraw);
    float* sbias = (float*)(smraw + 2 * G_STAGE);

    const int tid = threadIdx.x;
    const int lane = tid & 31, wid = tid >> 5;
    const int n0 = blockIdx.x * 128;
    const int m0 = blockIdx.y * 256;
    const int wm = (wid >> 2) * 64;    // 4 m-groups of 64
    const int wn = (wid & 3) * 32;     // 4 n-groups of 32

    if (tid < 128) sbias[tid] = b1[n0 + tid] + b2[n0 + tid];

    float acc[4][4][4];
#pragma unroll
    for (int i = 0; i < 4; i++)
#pragma unroll
        for (int j = 0; j < 4; j++)
#pragma unroll
            for (int q = 0; q < 4; q++) acc[i][j][q] = 0.f;

    gemm_issue_loads(sbase, 0, m0, n0, tid);

    const uint32_t a_row = wm + (lane & 15);
    const uint32_t a_coh = (lane >> 4) << 4;
    const uint32_t b_rlo = (lane >> 4) * 8 + (lane & 7);
    const uint32_t b_coh = ((lane >> 3) & 1) << 4;

    for (int c = 0; c < nch; c++) {
        if (c < nch - 1) {
            gemm_issue_loads(sbase + ((c + 1) & 1) * G_STAGE, c + 1, m0, n0, tid);
            cp_wait<1>();
        } else {
            cp_wait<0>();
        }
        __syncthreads();

        const uint32_t buf = sbase + (c & 1) * G_STAGE;
        const uint32_t Ahi_b = buf;
        const uint32_t Alo_b = buf + A_TILE;
        const uint32_t Whi_b = buf + 2 * A_TILE;
        const uint32_t Wlo_b = buf + 2 * A_TILE + W_TILE;

#pragma unroll
        for (int ks = 0; ks < 4; ks++) {
            const uint32_t kso = ks * 32;
            uint32_t ah[4][4], bh[4][2];
#pragma unroll
            for (int mt = 0; mt < 4; mt++)
                LDSM4(ah[mt], Ahi_b + (a_row + mt * 16) * TROW + kso + a_coh);
#pragma unroll
            for (int g = 0; g < 2; g++) {
                uint32_t t4[4];
                LDSM4(t4, Whi_b + (wn + g * 16 + b_rlo) * TROW + kso + b_coh);
                bh[g * 2][0] = t4[0]; bh[g * 2][1] = t4[1];
                bh[g * 2 + 1][0] = t4[2]; bh[g * 2 + 1][1] = t4[3];
            }
#pragma unroll
            for (int mt = 0; mt < 4; mt++)
#pragma unroll
                for (int nt = 0; nt < 4; nt++)
                    MMA16816(acc[mt][nt], ah[mt], bh[nt]);

            uint32_t bl[4][2];
#pragma unroll
            for (int g = 0; g < 2; g++) {
                uint32_t t4[4];
                LDSM4(t4, Wlo_b + (wn + g * 16 + b_rlo) * TROW + kso + b_coh);
                bl[g * 2][0] = t4[0]; bl[g * 2][1] = t4[1];
                bl[g * 2 + 1][0] = t4[2]; bl[g * 2 + 1][1] = t4[3];
            }
#pragma unroll
            for (int mt = 0; mt < 4; mt++)
#pragma unroll
                for (int nt = 0; nt < 4; nt++)
                    MMA16816(acc[mt][nt], ah[mt], bl[nt]);

            uint32_t al[4][4];
#pragma unroll
            for (int mt = 0; mt < 4; mt++)
                LDSM4(al[mt], Alo_b + (a_row + mt * 16) * TROW + kso + a_coh);
#pragma unroll
            for (int mt = 0; mt < 4; mt++)
#pragma unroll
                for (int nt = 0; nt < 4; nt++)
                    MMA16816(acc[mt][nt], al[mt], bh[nt]);
        }
        __syncthreads();
    }

    const int r_lo = lane >> 2;
    const int cpos = (lane & 3) * 2;
#pragma unroll
    for (int mt = 0; mt < 4; mt++) {
        int row0 = m0 + wm + mt * 16 + r_lo;
#pragma unroll
        for (int nt = 0; nt < 4; nt++) {
            int cl = wn + nt * 8 + cpos;
            float bx = sbias[cl], by = sbias[cl + 1];
            float2 v0 = make_float2(acc[mt][nt][0] + bx, acc[mt][nt][1] + by);
            float2 v1 = make_float2(acc[mt][nt][2] + bx, acc[mt][nt][3] + by);
            *(float2*)&g_xg[(size_t)row0 * GG + n0 + cl] = v0;
            *(float2*)&g_xg[(size_t)(row0 + 8) * GG + n0 + cl] = v1;
        }
    }
}

// ---------------- persistent recurrence: 8 warps, k-split pairs (r16 best, unchanged) ----------------
#define WROW 2064
#define WS_B (32 * WROW)
#define RROW 144
#define RBUF_B (16 * RROW)
#define RSTG_B (2 * RBUF_B)
#define NBUF 2
#define WARP_STG (NBUF * RSTG_B)
#define CMB_OFF (2 * WS_B + 8 * WARP_STG)
#define CMB_B (4 * 32 * 16 * 4)
#define REC_SMEM (CMB_OFF + CMB_B)

__device__ __forceinline__ void rec_stage_w(uint32_t dst, const __nv_bfloat16* ghi,
                                            const __nv_bfloat16* glo,
                                            int wb, int wk, int c, int lane) {
#pragma unroll
    for (int i = 0; i < 4; i++) {
        int idx = lane + i * 32;
        int r = idx >> 3, s = idx & 7;
        uint32_t d = dst + r * RROW + s * 16;
        size_t so = (size_t)(wb * 16 + r) * 1024 + wk * 512 + c * 64 + s * 8;
        cp_async16(d, ghi + so);
        cp_async16(d + RBUF_B, glo + so);
    }
    cp_commit();
}

template<int LAYER>
__global__ void __launch_bounds__(256, 1)
lstm_rec_tc(float* __restrict__ out_ext)
{
    extern __shared__ char smraw[];
    const uint32_t sb = smem_u32(smraw);
    const uint32_t ws_hi = sb;
    const uint32_t ws_lo = sb + WS_B;
    float* cmb = (float*)(smraw + CMB_OFF);

    const int tid = threadIdx.x;
    const int lane = tid & 31, wid = tid >> 5;
    const int wb = wid & 3;
    const int wk = wid >> 2;
    const int j0 = blockIdx.x * 8;
    const uint32_t wstg = sb + 2 * WS_B + wid * WARP_STG;

    {
        const int tt = tid & 127;
        const __nv_bfloat16* src = (tid < 128) ? g_Rhi : g_Rlo;
        const uint32_t dstb = (tid < 128) ? ws_hi : ws_lo;
#pragma unroll 4
        for (int n = 0; n < 32; n++) {
            int grow = ((n >> 3) << 10) + j0 + (n & 7);
            cp_async16(dstb + n * WROW + tt * 16, src + ((size_t)grow << 10) + tt * 8);
        }
    }
    cp_commit(); cp_wait<0>();
    __syncthreads();

    const uint32_t a_off = (lane & 15) * RROW + ((lane >> 4) << 4);
    const uint32_t w_off = ((lane >> 4) * 8 + (lane & 7)) * WROW + (((lane >> 3) & 1) << 4);

    const int r0 = lane >> 2;
    const int c0 = (lane & 3) * 2;
    const int bA = wb * 16 + r0;
    const int bB = bA + 8;
    const int jj = j0 + c0;

    float cst[4] = {0.f, 0.f, 0.f, 0.f};
    unsigned gen = 0;

    for (int t = 0; t < TT; t++) {
        const __nv_bfloat16* ghi_in = g_ghi[t & 1];
        const __nv_bfloat16* glo_in = g_glo[t & 1];
        __nv_bfloat16* ghi_out = g_ghi[(t + 1) & 1];
        __nv_bfloat16* glo_out = g_glo[(t + 1) & 1];

        float2 xgv[2][4];
        if (wk == 0) {
#pragma unroll
            for (int rp = 0; rp < 2; rp++) {
                size_t base = ((size_t)t * BB + (rp ? bB : bA)) * GG + jj;
#pragma unroll
                for (int g = 0; g < 4; g++)
                    xgv[rp][g] = *(const float2*)&g_xg[base + (size_t)g * HH];
            }
        }

        float acc[4][4], accC[4][4];
#pragma unroll
        for (int nt = 0; nt < 4; nt++)
#pragma unroll
            for (int q = 0; q < 4; q++) { acc[nt][q] = 0.f; accC[nt][q] = 0.f; }

        rec_stage_w(wstg, ghi_in, glo_in, wb, wk, 0, lane);

        for (int c = 0; c < 8; c++) {
            if (c < 7) {
                rec_stage_w(wstg + ((c + 1) & 1) * RSTG_B, ghi_in, glo_in, wb, wk, c + 1, lane);
                cp_wait<1>();
            } else {
                cp_wait<0>();
            }
            __syncwarp();

            const uint32_t abuf = wstg + (c & 1) * RSTG_B;
#pragma unroll
            for (int kl = 0; kl < 4; kl++) {
                const uint32_t Aad = abuf + a_off + kl * 32;
                const uint32_t kby = (uint32_t)(wk * 512 + c * 64 + kl * 16) * 2;

                uint32_t ah[4], al[4], bh[4][2], bl[4][2];
                LDSM4(ah, Aad);
                LDSM4(al, Aad + RBUF_B);
                {
                    uint32_t t4[4];
                    LDSM4(t4, ws_hi + w_off + kby);
                    bh[0][0] = t4[0]; bh[0][1] = t4[1]; bh[1][0] = t4[2]; bh[1][1] = t4[3];
                    LDSM4(t4, ws_hi + 16 * WROW + w_off + kby);
                    bh[2][0] = t4[0]; bh[2][1] = t4[1]; bh[3][0] = t4[2]; bh[3][1] = t4[3];
                    LDSM4(t4, ws_lo + w_off + kby);
                    bl[0][0] = t4[0]; bl[0][1] = t4[1]; bl[1][0] = t4[2]; bl[1][1] = t4[3];
                    LDSM4(t4, ws_lo + 16 * WROW + w_off + kby);
                    bl[2][0] = t4[0]; bl[2][1] = t4[1]; bl[3][0] = t4[2]; bl[3][1] = t4[3];
                }
#pragma unroll
                for (int nt = 0; nt < 4; nt++) {
                    MMA16816(acc[nt],  ah, bh[nt]);
                    MMA16816(accC[nt], al, bh[nt]);
                    MMA16816(accC[nt], ah, bl[nt]);
                }
            }
        }

        if (wk == 1) {
            float* p = cmb + (wb * 32 + lane) * 16;
#pragma unroll
            for (int nt = 0; nt < 4; nt++)
                *(float4*)(p + nt * 4) = make_float4(acc[nt][0] + accC[nt][0],
                                                     acc[nt][1] + accC[nt][1],
                                                     acc[nt][2] + accC[nt][2],
                                                     acc[nt][3] + accC[nt][3]);
        }
        BARPAIR(1 + wb);

        if (wk == 0) {
            float* p = cmb + (wb * 32 + lane) * 16;
#pragma unroll
            for (int nt = 0; nt < 4; nt++) {
                float4 v = *(float4*)(p + nt * 4);
                acc[nt][0] += accC[nt][0] + v.x;
                acc[nt][1] += accC[nt][1] + v.y;
                acc[nt][2] += accC[nt][2] + v.z;
                acc[nt][3] += accC[nt][3] + v.w;
            }

#pragma unroll
            for (int rp = 0; rp < 2; rp++) {
                const int b = rp ? bB : bA;
                float hn[2];
#pragma unroll
                for (int cc = 0; cc < 2; cc++) {
                    const int q = rp * 2 + cc;
                    float pi = acc[0][q] + (cc ? xgv[rp][0].y : xgv[rp][0].x);
                    float pf = acc[1][q] + (cc ? xgv[rp][1].y : xgv[rp][1].x);
                    float pg = acc[2][q] + (cc ? xgv[rp][2].y : xgv[rp][2].x);
                    float po = acc[3][q] + (cc ? xgv[rp][3].y : xgv[rp][3].x);
                    float ig = 1.f / (1.f + expf(-pi));
                    float fg = 1.f / (1.f + expf(-pf));
                    float gc = tanhf(pg);
                    float og = 1.f / (1.f + expf(-po));
                    float cn = fg * cst[q] + ig * gc;
                    cst[q] = cn;
                    hn[cc] = og * tanhf(cn);
                }
                __nv_bfloat16 h0 = __float2bfloat16(hn[0]);
                __nv_bfloat16 h1 = __float2bfloat16(hn[1]);
                __nv_bfloat16 l0 = __float2bfloat16(hn[0] - __bfloat162float(h0));
                __nv_bfloat16 l1 = __float2bfloat16(hn[1] - __bfloat162float(h1));
                *(__nv_bfloat162*)&ghi_out[(size_t)b * HH + jj] = __nv_bfloat162(h0, h1);
                *(__nv_bfloat162*)&glo_out[(size_t)b * HH + jj] = __nv_bfloat162(l0, l1);
                if (LAYER == 0) {
                    size_t arow = (((size_t)t * BB + b) << 10) + jj;
                    *(__nv_bfloat162*)&g_Ahi[arow] = __nv_bfloat162(h0, h1);
                    *(__nv_bfloat162*)&g_Alo[arow] = __nv_bfloat162(l0, l1);
                } else {
                    *(float2*)&out_ext[((size_t)b * TT + t) * HH + jj] = make_float2(hn[0], hn[1]);
                }
            }
        }

        // ---- grid barrier (central atomic, proven best) ----
        __threadfence();
        __syncthreads();
        gen++;
        if (tid == 0) {
            if (atomicAdd(&g_cnt, 1u) == NCTA - 1) {
                g_cnt = 0u;
                __threadfence();
                *(volatile unsigned*)&g_gen = gen;
            } else {
                while (*(volatile unsigned*)&g_gen < gen) { }
                __threadfence();
            }
        }
        __syncthreads();
    }
}

// ---------------- launch ----------------
extern "C" void kernel_launch(void* const* d_in, const int* in_sizes, int n_in,
                              void* d_out, int out_size)
{
    (void)in_sizes; (void)n_in; (void)out_size;
    const float* x     = (const float*)d_in[0];
    const float* W_ih0 = (const float*)d_in[1];
    const float* W_hh0 = (const float*)d_in[2];
    const float* b_ih0 = (const float*)d_in[3];
    const float* b_hh0 = (const float*)d_in[4];
    const float* W_ih1 = (const float*)d_in[5];
    const float* W_hh1 = (const float*)d_in[6];
    const float* b_ih1 = (const float*)d_in[7];
    const float* b_hh1 = (const float*)d_in[8];
    float* out = (float*)d_out;

    cudaFuncSetAttribute(gemm_bf16_split, cudaFuncAttributeMaxDynamicSharedMemorySize, GEMM_SMEM);
    cudaFuncSetAttribute(lstm_rec_tc<0>, cudaFuncAttributeMaxDynamicSharedMemorySize, REC_SMEM);
    cudaFuncSetAttribute(lstm_rec_tc<1>, cudaFuncAttributeMaxDynamicSharedMemorySize, REC_SMEM);

    dim3 gemm_grid(GG / 128, (TT * BB) / 256);   // 32 x 128 = 4096 CTAs
    const int nch0 = (DIN + 63) / 64;
    const int nch1 = 16;
    const size_t nW = (size_t)GG << 10;
    const int gridW = (int)((nW + 255) / 256);
    const int gridAll0 = (int)((NWELEM + NZ + NAELEM + 255) / 256);
    const int gridAll1 = (int)((NWELEM + NZ + 255) / 256);

    // ---- Layer 0 ----  (our launch index 3 = lstm_rec_tc<0> -> ncu capture target)
    convW<<<gridW, 256>>>(W_ih0, DIN);                                   // 0
    conv_all<<<gridAll0, 256>>>(x, W_hh0, 1);                            // 1
    gemm_bf16_split<<<gemm_grid, 512, GEMM_SMEM>>>(b_ih0, b_hh0, nch0);  // 2
    lstm_rec_tc<0><<<NCTA, 256, REC_SMEM>>>(out);                        // 3 <- profiled
    // ---- Layer 1 ----
    convW<<<gridW, 256>>>(W_ih1, HH);                                    // 4
    conv_all<<<gridAll1, 256>>>(nullptr, W_hh1, 0);                      // 5
    gemm_bf16_split<<<gemm_grid, 512, GEMM_SMEM>>>(b_ih1, b_hh1, nch1);  // 6
    lstm_rec_tc<1><<<NCTA, 256, REC_SMEM>>>(out);                        // 7
}